// round 9
// baseline (speedup 1.0000x reference)
#include <cuda_runtime.h>
#include <cstdint>

#define NN 50000
#define NE 600000
#define HF 128
#define NC 10
#define NBLK ((NN + 511) / 512)   // 98 scan blocks

// ---------------- scratch (static device globals; no allocation) ----------------
__device__ __align__(16) float d_g[(size_t)NN * HF];    // dinv*(xW^T+b)
__device__ __align__(16) float d_h[(size_t)NN * HF];    // conv output (h1 then h2)
__device__ int   d_deg[NN];      // row-degree + 1 (norm)
__device__ float d_dinv[NN];
__device__ int   d_cnt[NN];      // col histogram (CSR)
__device__ int   d_start[NN];    // CSR offsets
__device__ int   d_ptr[NN];      // CSR fill cursors
__device__ int   d_csr[NE];      // source row per CSR slot
__device__ int   d_bsum[128];    // scan block sums
__device__ int   d_boff[128];    // scan block offsets
__device__ float d_loss;

#define FFMA2(acc, a, b) asm("fma.rn.f32x2 %0, %1, %2, %0;" : "+l"(acc) : "l"(a), "l"(b))

// ---------------- init ----------------
__global__ void k_init() {
    int i = blockIdx.x * blockDim.x + threadIdx.x;
    if (i < NN) { d_deg[i] = 1; d_cnt[i] = 0; }
    if (i == 0) d_loss = 0.f;
}

// row-degree (norm) + col histogram (CSR) in one pass
__global__ void k_hist(const int* __restrict__ row, const int* __restrict__ col) {
    int e = blockIdx.x * blockDim.x + threadIdx.x;
    if (e < NE) {
        atomicAdd(&d_deg[row[e]], 1);
        atomicAdd(&d_cnt[col[e]], 1);
    }
}

__global__ void k_dinv() {
    int i = blockIdx.x * blockDim.x + threadIdx.x;
    if (i < NN) d_dinv[i] = rsqrtf((float)d_deg[i]);
}

// ---------------- multi-block exclusive scan of d_cnt ----------------
// phase 1: 98 blocks x 256 threads, 2 elements/thread -> local scan + block sums
__global__ void k_scan1() {
    __shared__ int wsum[8];
    const int t = threadIdx.x;
    const int base = blockIdx.x * 512 + t * 2;
    int c0 = (base < NN) ? d_cnt[base] : 0;
    int c1 = (base + 1 < NN) ? d_cnt[base + 1] : 0;
    int s = c0 + c1;
    int v = s;
#pragma unroll
    for (int o = 1; o < 32; o <<= 1) {
        int u = __shfl_up_sync(0xffffffffu, v, o);
        if ((t & 31) >= o) v += u;
    }
    if ((t & 31) == 31) wsum[t >> 5] = v;
    __syncthreads();
    if (t < 8) {
        int w = wsum[t];
#pragma unroll
        for (int o = 1; o < 8; o <<= 1) {
            int u = __shfl_up_sync(0xffu, w, o);
            if (t >= o) w += u;
        }
        wsum[t] = w;
    }
    __syncthreads();
    int pre = v - s + ((t >= 32) ? wsum[(t >> 5) - 1] : 0);
    if (base < NN) d_start[base] = pre;
    if (base + 1 < NN) d_start[base + 1] = pre + c0;
    if (t == 255) d_bsum[blockIdx.x] = wsum[7];
}

// phase 2: single warp scans the 98 block sums
__global__ void k_scan2() {
    const int l = threadIdx.x;
    int c[4];
    int s = 0;
#pragma unroll
    for (int i = 0; i < 4; i++) {
        int idx = l * 4 + i;
        c[i] = (idx < NBLK) ? d_bsum[idx] : 0;
        s += c[i];
    }
    int v = s;
#pragma unroll
    for (int o = 1; o < 32; o <<= 1) {
        int u = __shfl_up_sync(0xffffffffu, v, o);
        if (l >= o) v += u;
    }
    int ex = v - s;
#pragma unroll
    for (int i = 0; i < 4; i++) {
        int idx = l * 4 + i;
        if (idx < NBLK) d_boff[idx] = ex;
        ex += c[i];
    }
}

// phase 3: add block offsets, init fill cursors
__global__ void k_scan3() {
    int i = blockIdx.x * blockDim.x + threadIdx.x;
    if (i < NN) {
        int v = d_start[i] + d_boff[i >> 9];
        d_start[i] = v;
        d_ptr[i] = v;
    }
}

__global__ void k_fill(const int* __restrict__ row, const int* __restrict__ col) {
    int e = blockIdx.x * blockDim.x + threadIdx.x;
    if (e < NE) {
        int c = col[e];
        int slot = atomicAdd(&d_ptr[c], 1);
        d_csr[slot] = row[e];
    }
}

// ---------------- node GEMM (f32x2 packed): g = dinv * (x @ W^T + b) ----------------
// Block: 64 rows x 128 cols, 256 threads, thread = 8 rows x 4 cols.
// Shared staged as float2 k-pairs, stride 17 float2 (pad) per row.
__global__ void k_gemm(const float* __restrict__ x, const float* __restrict__ W,
                       const float* __restrict__ b) {
    __shared__ __align__(16) float2 xs2[64 * 17];
    __shared__ __align__(16) float2 ws2[128 * 17];
    const int tid = threadIdx.x;
    const int tc = tid & 31;
    const int tr = tid >> 5;
    const int rb = blockIdx.x * 64;

    unsigned long long acc2[8][4];
#pragma unroll
    for (int i = 0; i < 8; i++)
#pragma unroll
        for (int j = 0; j < 4; j++) acc2[i][j] = 0ull;

    for (int kc = 0; kc < HF; kc += 32) {
#pragma unroll
        for (int l = 0; l < 2; l++) {
            int idx = tid + l * 256;      // float4 index, 0..511
            int r = idx >> 3;
            int q = idx & 7;
            float4 v = make_float4(0.f, 0.f, 0.f, 0.f);
            if (rb + r < NN) v = *(const float4*)(x + (size_t)(rb + r) * HF + kc + q * 4);
            xs2[r * 17 + q * 2 + 0] = make_float2(v.x, v.y);
            xs2[r * 17 + q * 2 + 1] = make_float2(v.z, v.w);
        }
#pragma unroll
        for (int l = 0; l < 4; l++) {
            int idx = tid + l * 256;      // float4 index, 0..1023
            int t = idx >> 3;
            int q = idx & 7;
            float4 v = *(const float4*)(W + (size_t)t * HF + kc + q * 4);
            ws2[t * 17 + q * 2 + 0] = make_float2(v.x, v.y);
            ws2[t * 17 + q * 2 + 1] = make_float2(v.z, v.w);
        }
        __syncthreads();
#pragma unroll
        for (int kq = 0; kq < 16; kq++) {
            unsigned long long wv[4];
#pragma unroll
            for (int j = 0; j < 4; j++)
                wv[j] = *(const unsigned long long*)&ws2[(tc + 32 * j) * 17 + kq];
#pragma unroll
            for (int i = 0; i < 8; i++) {
                unsigned long long xv =
                    *(const unsigned long long*)&xs2[(tr * 8 + i) * 17 + kq];
#pragma unroll
                for (int j = 0; j < 4; j++) FFMA2(acc2[i][j], xv, wv[j]);
            }
        }
        __syncthreads();
    }

#pragma unroll
    for (int i = 0; i < 8; i++) {
        int r = rb + tr * 8 + i;
        if (r >= NN) break;
        float dv = d_dinv[r];
#pragma unroll
        for (int j = 0; j < 4; j++) {
            int c0 = tc + 32 * j;
            float lo, hi;
            asm("mov.b64 {%0, %1}, %2;" : "=f"(lo), "=f"(hi) : "l"(acc2[i][j]));
            d_g[(size_t)r * HF + c0] = dv * (lo + hi + b[c0]);
        }
    }
}

// ---------------- CSR aggregate: h[n] = dinv[n] * (g[n] + sum_{e: col=n} g[row_e]) ----------------
__global__ void k_aggr() {
    int gw = (blockIdx.x * blockDim.x + threadIdx.x) >> 5;
    if (gw >= NN) return;
    const int lane = threadIdx.x & 31;
    const int s = d_start[gw];
    const int cnt = d_cnt[gw];
    const float4* gp = (const float4*)d_g;

    float4 acc = __ldg(gp + (size_t)gw * 32 + lane);   // self loop
    for (int j0 = 0; j0 < cnt; j0 += 32) {
        int r = 0;
        if (j0 + lane < cnt) r = __ldg(d_csr + s + j0 + lane);
        int m = min(32, cnt - j0);
        int k = 0;
        for (; k + 4 <= m; k += 4) {
            int r0 = __shfl_sync(0xffffffffu, r, k + 0);
            int r1 = __shfl_sync(0xffffffffu, r, k + 1);
            int r2 = __shfl_sync(0xffffffffu, r, k + 2);
            int r3 = __shfl_sync(0xffffffffu, r, k + 3);
            float4 v0 = __ldg(gp + (size_t)r0 * 32 + lane);
            float4 v1 = __ldg(gp + (size_t)r1 * 32 + lane);
            float4 v2 = __ldg(gp + (size_t)r2 * 32 + lane);
            float4 v3 = __ldg(gp + (size_t)r3 * 32 + lane);
            acc.x += v0.x + v1.x + v2.x + v3.x;
            acc.y += v0.y + v1.y + v2.y + v3.y;
            acc.z += v0.z + v1.z + v2.z + v3.z;
            acc.w += v0.w + v1.w + v2.w + v3.w;
        }
        for (; k < m; k++) {
            int rr = __shfl_sync(0xffffffffu, r, k);
            float4 v = __ldg(gp + (size_t)rr * 32 + lane);
            acc.x += v.x; acc.y += v.y; acc.z += v.z; acc.w += v.w;
        }
    }
    float dv = d_dinv[gw];
    acc.x *= dv; acc.y *= dv; acc.z *= dv; acc.w *= dv;
    ((float4*)d_h)[(size_t)gw * 32 + lane] = acc;
}

// ---------------- edge head: 2 edges per thread, f32x2 packed ----------------
__global__ void k_logits(const float* __restrict__ Wfc, const float* __restrict__ bfc,
                         const int* __restrict__ row, const int* __restrict__ col,
                         const int* __restrict__ label, float* __restrict__ logits) {
    __shared__ __align__(16) float ws[NC * 256];
    __shared__ float bs[NC];
    __shared__ float red[256];
    const int tid = threadIdx.x;
    for (int i = tid; i < NC * 256; i += 256) ws[i] = Wfc[i];
    if (tid < NC) bs[tid] = bfc[tid];
    __syncthreads();

    const int e0 = blockIdx.x * 512 + tid;
    const int e1 = e0 + 256;
    const bool v0 = e0 < NE;
    const bool v1 = e1 < NE;
    int r0 = 0, c0 = 0, r1 = 0, c1 = 0;
    if (v0) { r0 = row[e0]; c0 = col[e0]; }
    if (v1) { r1 = row[e1]; c1 = col[e1]; }

    unsigned long long a0[NC], a1[NC];
#pragma unroll
    for (int cc = 0; cc < NC; cc++) { a0[cc] = 0ull; a1[cc] = 0ull; }

    const ulonglong2* pr0 = (const ulonglong2*)(d_h + (size_t)r0 * HF);
    const ulonglong2* pr1 = (const ulonglong2*)(d_h + (size_t)r1 * HF);
#pragma unroll
    for (int q = 0; q < 32; q++) {
        ulonglong2 xa = __ldg(pr0 + q);
        ulonglong2 xb = __ldg(pr1 + q);
#pragma unroll
        for (int cc = 0; cc < NC; cc++) {
            ulonglong2 wv = *(const ulonglong2*)&ws[cc * 256 + q * 4];
            FFMA2(a0[cc], xa.x, wv.x);
            FFMA2(a0[cc], xa.y, wv.y);
            FFMA2(a1[cc], xb.x, wv.x);
            FFMA2(a1[cc], xb.y, wv.y);
        }
    }
    const ulonglong2* pc0 = (const ulonglong2*)(d_h + (size_t)c0 * HF);
    const ulonglong2* pc1 = (const ulonglong2*)(d_h + (size_t)c1 * HF);
#pragma unroll
    for (int q = 0; q < 32; q++) {
        ulonglong2 xa = __ldg(pc0 + q);
        ulonglong2 xb = __ldg(pc1 + q);
#pragma unroll
        for (int cc = 0; cc < NC; cc++) {
            ulonglong2 wv = *(const ulonglong2*)&ws[cc * 256 + 128 + q * 4];
            FFMA2(a0[cc], xa.x, wv.x);
            FFMA2(a0[cc], xa.y, wv.y);
            FFMA2(a1[cc], xb.x, wv.x);
            FFMA2(a1[cc], xb.y, wv.y);
        }
    }

    float myloss = 0.f;
#pragma unroll
    for (int half = 0; half < 2; half++) {
        const unsigned long long* ap = half ? a1 : a0;
        const bool vv = half ? v1 : v0;
        const int ee = half ? e1 : e0;
        if (!vv) continue;
        float acc[NC];
#pragma unroll
        for (int cc = 0; cc < NC; cc++) {
            float lo, hi;
            asm("mov.b64 {%0, %1}, %2;" : "=f"(lo), "=f"(hi) : "l"(ap[cc]));
            acc[cc] = bs[cc] + lo + hi;
        }
        float m = acc[0];
#pragma unroll
        for (int cc = 1; cc < NC; cc++) m = fmaxf(m, acc[cc]);
        float s = 0.f;
#pragma unroll
        for (int cc = 0; cc < NC; cc++) s += expf(acc[cc] - m);
        float lse = m + logf(s);
        myloss += lse - acc[label[ee]];
        float* lp = logits + (size_t)ee * NC;
#pragma unroll
        for (int cc = 0; cc < NC; cc++) lp[cc] = acc[cc];
    }

    red[tid] = myloss;
    __syncthreads();
    for (int s2 = 128; s2 > 0; s2 >>= 1) {
        if (tid < s2) red[tid] += red[tid + s2];
        __syncthreads();
    }
    if (tid == 0) atomicAdd(&d_loss, red[0]);
}

__global__ void k_final(float* __restrict__ loss_out) {
    if (loss_out) loss_out[0] = d_loss * (1.0f / (float)NE);
}

// ---------------- launch ----------------
extern "C" void kernel_launch(void* const* d_in, const int* in_sizes, int n_in,
                              void* d_out, int out_size) {
    const float* feat = (const float*)d_in[0];
    const float* W1   = (const float*)d_in[1];
    const float* b1   = (const float*)d_in[2];
    const float* W2   = (const float*)d_in[3];
    const float* b2   = (const float*)d_in[4];
    const float* Wfc  = (const float*)d_in[5];
    const float* bfc  = (const float*)d_in[6];
    const int*   row  = (const int*)d_in[7];
    const int*   col  = (const int*)d_in[8];
    const int*   lab  = (const int*)d_in[9];

    float* out = (float*)d_out;
    float* lossp;
    float* logits;
    if (out_size == NE * NC + 1) { lossp = out; logits = out + 1; }
    else                         { lossp = nullptr; logits = out; }

    void* ph = nullptr;
    cudaGetSymbolAddress(&ph, d_h);
    const float* h1 = (const float*)ph;

    const int TB = 256;
    const int nb_nodes = (NN + TB - 1) / TB;
    const int nb_edges = (NE + TB - 1) / TB;
    const int nb_gemm  = (NN + 63) / 64;
    const int nb_aggr  = (NN * 32 + TB - 1) / TB;
    const int nb_log   = (NE + 511) / 512;

    k_init<<<nb_nodes, TB>>>();
    k_hist<<<nb_edges, TB>>>(row, col);
    k_dinv<<<nb_nodes, TB>>>();
    k_scan1<<<NBLK, 256>>>();
    k_scan2<<<1, 32>>>();
    k_scan3<<<nb_nodes, TB>>>();
    k_fill<<<nb_edges, TB>>>(row, col);

    // conv 1
    k_gemm<<<nb_gemm, TB>>>(feat, W1, b1);
    k_aggr<<<nb_aggr, TB>>>();            // -> d_h = h1

    // conv 2
    k_gemm<<<nb_gemm, TB>>>(h1, W2, b2);
    k_aggr<<<nb_aggr, TB>>>();            // -> d_h = h2

    // edge head
    k_logits<<<nb_log, TB>>>(Wfc, bfc, row, col, lab, logits);
    k_final<<<1, 1>>>(lossp);
}

// round 10
// speedup vs baseline: 1.0003x; 1.0003x over previous
#include <cuda_runtime.h>
#include <cstdint>

#define NN 50000
#define NE 600000
#define HF 128
#define NC 10
#define NBLK ((NN + 511) / 512)   // 98 scan blocks

// ---------------- scratch (static device globals; no allocation) ----------------
__device__ __align__(16) float d_g[(size_t)NN * HF];    // dinv*(xW^T+b)
__device__ __align__(16) float d_h[(size_t)NN * HF];    // conv output (h1 then h2)
__device__ int   d_deg[NN];      // row-degree + 1 (norm)
__device__ float d_dinv[NN];
__device__ int   d_cnt[NN];      // col histogram (CSR)
__device__ int   d_start[NN];    // CSR offsets
__device__ int   d_ptr[NN];      // CSR fill cursors
__device__ int   d_csr[NE];      // source row per CSR slot
__device__ int   d_bsum[128];    // scan block sums
__device__ int   d_boff[128];    // scan block offsets
__device__ float d_loss;

#define FFMA2(acc, a, b) asm("fma.rn.f32x2 %0, %1, %2, %0;" : "+l"(acc) : "l"(a), "l"(b))

// ---------------- init ----------------
__global__ void k_init() {
    int i = blockIdx.x * blockDim.x + threadIdx.x;
    if (i < NN) { d_deg[i] = 1; d_cnt[i] = 0; }
    if (i == 0) d_loss = 0.f;
}

// row-degree (norm) + col histogram (CSR) in one pass
__global__ void k_hist(const int* __restrict__ row, const int* __restrict__ col) {
    int e = blockIdx.x * blockDim.x + threadIdx.x;
    if (e < NE) {
        atomicAdd(&d_deg[row[e]], 1);
        atomicAdd(&d_cnt[col[e]], 1);
    }
}

__global__ void k_dinv() {
    int i = blockIdx.x * blockDim.x + threadIdx.x;
    if (i < NN) d_dinv[i] = rsqrtf((float)d_deg[i]);
}

// ---------------- multi-block exclusive scan of d_cnt ----------------
// phase 1: 98 blocks x 256 threads, 2 elements/thread -> local scan + block sums
__global__ void k_scan1() {
    __shared__ int wsum[8];
    const int t = threadIdx.x;
    const int base = blockIdx.x * 512 + t * 2;
    int c0 = (base < NN) ? d_cnt[base] : 0;
    int c1 = (base + 1 < NN) ? d_cnt[base + 1] : 0;
    int s = c0 + c1;
    int v = s;
#pragma unroll
    for (int o = 1; o < 32; o <<= 1) {
        int u = __shfl_up_sync(0xffffffffu, v, o);
        if ((t & 31) >= o) v += u;
    }
    if ((t & 31) == 31) wsum[t >> 5] = v;
    __syncthreads();
    if (t < 8) {
        int w = wsum[t];
#pragma unroll
        for (int o = 1; o < 8; o <<= 1) {
            int u = __shfl_up_sync(0xffu, w, o);
            if (t >= o) w += u;
        }
        wsum[t] = w;
    }
    __syncthreads();
    int pre = v - s + ((t >= 32) ? wsum[(t >> 5) - 1] : 0);
    if (base < NN) d_start[base] = pre;
    if (base + 1 < NN) d_start[base + 1] = pre + c0;
    if (t == 255) d_bsum[blockIdx.x] = wsum[7];
}

// phase 2: single warp scans the 98 block sums
__global__ void k_scan2() {
    const int l = threadIdx.x;
    int c[4];
    int s = 0;
#pragma unroll
    for (int i = 0; i < 4; i++) {
        int idx = l * 4 + i;
        c[i] = (idx < NBLK) ? d_bsum[idx] : 0;
        s += c[i];
    }
    int v = s;
#pragma unroll
    for (int o = 1; o < 32; o <<= 1) {
        int u = __shfl_up_sync(0xffffffffu, v, o);
        if (l >= o) v += u;
    }
    int ex = v - s;
#pragma unroll
    for (int i = 0; i < 4; i++) {
        int idx = l * 4 + i;
        if (idx < NBLK) d_boff[idx] = ex;
        ex += c[i];
    }
}

// phase 3: add block offsets, init fill cursors
__global__ void k_scan3() {
    int i = blockIdx.x * blockDim.x + threadIdx.x;
    if (i < NN) {
        int v = d_start[i] + d_boff[i >> 9];
        d_start[i] = v;
        d_ptr[i] = v;
    }
}

__global__ void k_fill(const int* __restrict__ row, const int* __restrict__ col) {
    int e = blockIdx.x * blockDim.x + threadIdx.x;
    if (e < NE) {
        int c = col[e];
        int slot = atomicAdd(&d_ptr[c], 1);
        d_csr[slot] = row[e];
    }
}

// ---------------- node GEMM (f32x2 packed): g = dinv * (x @ W^T + b) ----------------
// Block: 64 rows x 128 cols, 256 threads, thread = 8 rows x 4 cols.
// Shared staged as float2 k-pairs, stride 17 float2 (pad) per row.
__global__ void k_gemm(const float* __restrict__ x, const float* __restrict__ W,
                       const float* __restrict__ b) {
    __shared__ __align__(16) float2 xs2[64 * 17];
    __shared__ __align__(16) float2 ws2[128 * 17];
    const int tid = threadIdx.x;
    const int tc = tid & 31;
    const int tr = tid >> 5;
    const int rb = blockIdx.x * 64;

    unsigned long long acc2[8][4];
#pragma unroll
    for (int i = 0; i < 8; i++)
#pragma unroll
        for (int j = 0; j < 4; j++) acc2[i][j] = 0ull;

    for (int kc = 0; kc < HF; kc += 32) {
#pragma unroll
        for (int l = 0; l < 2; l++) {
            int idx = tid + l * 256;      // float4 index, 0..511
            int r = idx >> 3;
            int q = idx & 7;
            float4 v = make_float4(0.f, 0.f, 0.f, 0.f);
            if (rb + r < NN) v = *(const float4*)(x + (size_t)(rb + r) * HF + kc + q * 4);
            xs2[r * 17 + q * 2 + 0] = make_float2(v.x, v.y);
            xs2[r * 17 + q * 2 + 1] = make_float2(v.z, v.w);
        }
#pragma unroll
        for (int l = 0; l < 4; l++) {
            int idx = tid + l * 256;      // float4 index, 0..1023
            int t = idx >> 3;
            int q = idx & 7;
            float4 v = *(const float4*)(W + (size_t)t * HF + kc + q * 4);
            ws2[t * 17 + q * 2 + 0] = make_float2(v.x, v.y);
            ws2[t * 17 + q * 2 + 1] = make_float2(v.z, v.w);
        }
        __syncthreads();
#pragma unroll
        for (int kq = 0; kq < 16; kq++) {
            unsigned long long wv[4];
#pragma unroll
            for (int j = 0; j < 4; j++)
                wv[j] = *(const unsigned long long*)&ws2[(tc + 32 * j) * 17 + kq];
#pragma unroll
            for (int i = 0; i < 8; i++) {
                unsigned long long xv =
                    *(const unsigned long long*)&xs2[(tr * 8 + i) * 17 + kq];
#pragma unroll
                for (int j = 0; j < 4; j++) FFMA2(acc2[i][j], xv, wv[j]);
            }
        }
        __syncthreads();
    }

#pragma unroll
    for (int i = 0; i < 8; i++) {
        int r = rb + tr * 8 + i;
        if (r >= NN) break;
        float dv = d_dinv[r];
#pragma unroll
        for (int j = 0; j < 4; j++) {
            int c0 = tc + 32 * j;
            float lo, hi;
            asm("mov.b64 {%0, %1}, %2;" : "=f"(lo), "=f"(hi) : "l"(acc2[i][j]));
            d_g[(size_t)r * HF + c0] = dv * (lo + hi + b[c0]);
        }
    }
}

// ---------------- CSR aggregate: h[n] = dinv[n] * (g[n] + sum_{e: col=n} g[row_e]) ----------------
__global__ void k_aggr() {
    int gw = (blockIdx.x * blockDim.x + threadIdx.x) >> 5;
    if (gw >= NN) return;
    const int lane = threadIdx.x & 31;
    const int s = d_start[gw];
    const int cnt = d_cnt[gw];
    const float4* gp = (const float4*)d_g;

    float4 acc = __ldg(gp + (size_t)gw * 32 + lane);   // self loop
    for (int j0 = 0; j0 < cnt; j0 += 32) {
        int r = 0;
        if (j0 + lane < cnt) r = __ldg(d_csr + s + j0 + lane);
        int m = min(32, cnt - j0);
        int k = 0;
        for (; k + 4 <= m; k += 4) {
            int r0 = __shfl_sync(0xffffffffu, r, k + 0);
            int r1 = __shfl_sync(0xffffffffu, r, k + 1);
            int r2 = __shfl_sync(0xffffffffu, r, k + 2);
            int r3 = __shfl_sync(0xffffffffu, r, k + 3);
            float4 v0 = __ldg(gp + (size_t)r0 * 32 + lane);
            float4 v1 = __ldg(gp + (size_t)r1 * 32 + lane);
            float4 v2 = __ldg(gp + (size_t)r2 * 32 + lane);
            float4 v3 = __ldg(gp + (size_t)r3 * 32 + lane);
            acc.x += v0.x + v1.x + v2.x + v3.x;
            acc.y += v0.y + v1.y + v2.y + v3.y;
            acc.z += v0.z + v1.z + v2.z + v3.z;
            acc.w += v0.w + v1.w + v2.w + v3.w;
        }
        for (; k < m; k++) {
            int rr = __shfl_sync(0xffffffffu, r, k);
            float4 v = __ldg(gp + (size_t)rr * 32 + lane);
            acc.x += v.x; acc.y += v.y; acc.z += v.z; acc.w += v.w;
        }
    }
    float dv = d_dinv[gw];
    acc.x *= dv; acc.y *= dv; acc.z *= dv; acc.w *= dv;
    ((float4*)d_h)[(size_t)gw * 32 + lane] = acc;
}

// ---------------- edge head: 2 edges per thread, f32x2 packed ----------------
__global__ void k_logits(const float* __restrict__ Wfc, const float* __restrict__ bfc,
                         const int* __restrict__ row, const int* __restrict__ col,
                         const int* __restrict__ label, float* __restrict__ logits) {
    __shared__ __align__(16) float ws[NC * 256];
    __shared__ float bs[NC];
    __shared__ float red[256];
    const int tid = threadIdx.x;
    for (int i = tid; i < NC * 256; i += 256) ws[i] = Wfc[i];
    if (tid < NC) bs[tid] = bfc[tid];
    __syncthreads();

    const int e0 = blockIdx.x * 512 + tid;
    const int e1 = e0 + 256;
    const bool v0 = e0 < NE;
    const bool v1 = e1 < NE;
    int r0 = 0, c0 = 0, r1 = 0, c1 = 0;
    if (v0) { r0 = row[e0]; c0 = col[e0]; }
    if (v1) { r1 = row[e1]; c1 = col[e1]; }

    unsigned long long a0[NC], a1[NC];
#pragma unroll
    for (int cc = 0; cc < NC; cc++) { a0[cc] = 0ull; a1[cc] = 0ull; }

    const ulonglong2* pr0 = (const ulonglong2*)(d_h + (size_t)r0 * HF);
    const ulonglong2* pr1 = (const ulonglong2*)(d_h + (size_t)r1 * HF);
#pragma unroll
    for (int q = 0; q < 32; q++) {
        ulonglong2 xa = __ldg(pr0 + q);
        ulonglong2 xb = __ldg(pr1 + q);
#pragma unroll
        for (int cc = 0; cc < NC; cc++) {
            ulonglong2 wv = *(const ulonglong2*)&ws[cc * 256 + q * 4];
            FFMA2(a0[cc], xa.x, wv.x);
            FFMA2(a0[cc], xa.y, wv.y);
            FFMA2(a1[cc], xb.x, wv.x);
            FFMA2(a1[cc], xb.y, wv.y);
        }
    }
    const ulonglong2* pc0 = (const ulonglong2*)(d_h + (size_t)c0 * HF);
    const ulonglong2* pc1 = (const ulonglong2*)(d_h + (size_t)c1 * HF);
#pragma unroll
    for (int q = 0; q < 32; q++) {
        ulonglong2 xa = __ldg(pc0 + q);
        ulonglong2 xb = __ldg(pc1 + q);
#pragma unroll
        for (int cc = 0; cc < NC; cc++) {
            ulonglong2 wv = *(const ulonglong2*)&ws[cc * 256 + 128 + q * 4];
            FFMA2(a0[cc], xa.x, wv.x);
            FFMA2(a0[cc], xa.y, wv.y);
            FFMA2(a1[cc], xb.x, wv.x);
            FFMA2(a1[cc], xb.y, wv.y);
        }
    }

    float myloss = 0.f;
#pragma unroll
    for (int half = 0; half < 2; half++) {
        const unsigned long long* ap = half ? a1 : a0;
        const bool vv = half ? v1 : v0;
        const int ee = half ? e1 : e0;
        if (!vv) continue;
        float acc[NC];
#pragma unroll
        for (int cc = 0; cc < NC; cc++) {
            float lo, hi;
            asm("mov.b64 {%0, %1}, %2;" : "=f"(lo), "=f"(hi) : "l"(ap[cc]));
            acc[cc] = bs[cc] + lo + hi;
        }
        float m = acc[0];
#pragma unroll
        for (int cc = 1; cc < NC; cc++) m = fmaxf(m, acc[cc]);
        float s = 0.f;
#pragma unroll
        for (int cc = 0; cc < NC; cc++) s += expf(acc[cc] - m);
        float lse = m + logf(s);
        myloss += lse - acc[label[ee]];
        float* lp = logits + (size_t)ee * NC;
#pragma unroll
        for (int cc = 0; cc < NC; cc++) lp[cc] = acc[cc];
    }

    red[tid] = myloss;
    __syncthreads();
    for (int s2 = 128; s2 > 0; s2 >>= 1) {
        if (tid < s2) red[tid] += red[tid + s2];
        __syncthreads();
    }
    if (tid == 0) atomicAdd(&d_loss, red[0]);
}

__global__ void k_final(float* __restrict__ loss_out) {
    if (loss_out) loss_out[0] = d_loss * (1.0f / (float)NE);
}

// ---------------- launch ----------------
extern "C" void kernel_launch(void* const* d_in, const int* in_sizes, int n_in,
                              void* d_out, int out_size) {
    const float* feat = (const float*)d_in[0];
    const float* W1   = (const float*)d_in[1];
    const float* b1   = (const float*)d_in[2];
    const float* W2   = (const float*)d_in[3];
    const float* b2   = (const float*)d_in[4];
    const float* Wfc  = (const float*)d_in[5];
    const float* bfc  = (const float*)d_in[6];
    const int*   row  = (const int*)d_in[7];
    const int*   col  = (const int*)d_in[8];
    const int*   lab  = (const int*)d_in[9];

    float* out = (float*)d_out;
    float* lossp;
    float* logits;
    if (out_size == NE * NC + 1) { lossp = out; logits = out + 1; }
    else                         { lossp = nullptr; logits = out; }

    void* ph = nullptr;
    cudaGetSymbolAddress(&ph, d_h);
    const float* h1 = (const float*)ph;

    const int TB = 256;
    const int nb_nodes = (NN + TB - 1) / TB;
    const int nb_edges = (NE + TB - 1) / TB;
    const int nb_gemm  = (NN + 63) / 64;
    const int nb_aggr  = (NN * 32 + TB - 1) / TB;
    const int nb_log   = (NE + 511) / 512;

    k_init<<<nb_nodes, TB>>>();
    k_hist<<<nb_edges, TB>>>(row, col);
    k_dinv<<<nb_nodes, TB>>>();
    k_scan1<<<NBLK, 256>>>();
    k_scan2<<<1, 32>>>();
    k_scan3<<<nb_nodes, TB>>>();
    k_fill<<<nb_edges, TB>>>(row, col);

    // conv 1
    k_gemm<<<nb_gemm, TB>>>(feat, W1, b1);
    k_aggr<<<nb_aggr, TB>>>();            // -> d_h = h1

    // conv 2
    k_gemm<<<nb_gemm, TB>>>(h1, W2, b2);
    k_aggr<<<nb_aggr, TB>>>();            // -> d_h = h2

    // edge head
    k_logits<<<nb_log, TB>>>(Wfc, bfc, row, col, lab, logits);
    k_final<<<1, 1>>>(lossp);
}

// round 11
// speedup vs baseline: 1.5789x; 1.5784x over previous
#include <cuda_runtime.h>
#include <cstdint>

#define NN 50000
#define NE 600000
#define HF 128
#define NC 10
#define PSTR 12                  // padded projection row stride (floats)
#define NBLK ((NN + 511) / 512)  // 98 scan blocks

// ---------------- scratch (static device globals; no allocation) ----------------
__device__ __align__(16) float d_g[(size_t)NN * HF];    // dinv*(xW^T+b)
__device__ __align__(16) float d_h[(size_t)NN * HF];    // conv output (h1 then h2)
__device__ __align__(16) float d_pr[(size_t)NN * PSTR]; // Wr@h2[n] + bfc
__device__ __align__(16) float d_pc[(size_t)NN * PSTR]; // Wc@h2[n]
__device__ int   d_deg[NN];      // row-degree + 1 (norm)
__device__ float d_dinv[NN];
__device__ int   d_cnt[NN];      // col histogram (CSR)
__device__ int   d_start[NN];    // CSR offsets
__device__ int   d_ptr[NN];      // CSR fill cursors
__device__ int   d_csr[NE];      // source row per CSR slot
__device__ int   d_bsum[128];    // scan block sums
__device__ int   d_boff[128];    // scan block offsets
__device__ float d_loss;

#define FFMA2(acc, a, b) asm("fma.rn.f32x2 %0, %1, %2, %0;" : "+l"(acc) : "l"(a), "l"(b))

// ---------------- init ----------------
__global__ void k_init() {
    int i = blockIdx.x * blockDim.x + threadIdx.x;
    if (i < NN) { d_deg[i] = 1; d_cnt[i] = 0; }
    if (i == 0) d_loss = 0.f;
}

// row-degree (norm) + col histogram (CSR) in one pass
__global__ void k_hist(const int* __restrict__ row, const int* __restrict__ col) {
    int e = blockIdx.x * blockDim.x + threadIdx.x;
    if (e < NE) {
        atomicAdd(&d_deg[row[e]], 1);
        atomicAdd(&d_cnt[col[e]], 1);
    }
}

__global__ void k_dinv() {
    int i = blockIdx.x * blockDim.x + threadIdx.x;
    if (i < NN) d_dinv[i] = rsqrtf((float)d_deg[i]);
}

// ---------------- multi-block exclusive scan of d_cnt ----------------
__global__ void k_scan1() {
    __shared__ int wsum[8];
    const int t = threadIdx.x;
    const int base = blockIdx.x * 512 + t * 2;
    int c0 = (base < NN) ? d_cnt[base] : 0;
    int c1 = (base + 1 < NN) ? d_cnt[base + 1] : 0;
    int s = c0 + c1;
    int v = s;
#pragma unroll
    for (int o = 1; o < 32; o <<= 1) {
        int u = __shfl_up_sync(0xffffffffu, v, o);
        if ((t & 31) >= o) v += u;
    }
    if ((t & 31) == 31) wsum[t >> 5] = v;
    __syncthreads();
    if (t < 8) {
        int w = wsum[t];
#pragma unroll
        for (int o = 1; o < 8; o <<= 1) {
            int u = __shfl_up_sync(0xffu, w, o);
            if (t >= o) w += u;
        }
        wsum[t] = w;
    }
    __syncthreads();
    int pre = v - s + ((t >= 32) ? wsum[(t >> 5) - 1] : 0);
    if (base < NN) d_start[base] = pre;
    if (base + 1 < NN) d_start[base + 1] = pre + c0;
    if (t == 255) d_bsum[blockIdx.x] = wsum[7];
}

__global__ void k_scan2() {
    const int l = threadIdx.x;
    int c[4];
    int s = 0;
#pragma unroll
    for (int i = 0; i < 4; i++) {
        int idx = l * 4 + i;
        c[i] = (idx < NBLK) ? d_bsum[idx] : 0;
        s += c[i];
    }
    int v = s;
#pragma unroll
    for (int o = 1; o < 32; o <<= 1) {
        int u = __shfl_up_sync(0xffffffffu, v, o);
        if (l >= o) v += u;
    }
    int ex = v - s;
#pragma unroll
    for (int i = 0; i < 4; i++) {
        int idx = l * 4 + i;
        if (idx < NBLK) d_boff[idx] = ex;
        ex += c[i];
    }
}

__global__ void k_scan3() {
    int i = blockIdx.x * blockDim.x + threadIdx.x;
    if (i < NN) {
        int v = d_start[i] + d_boff[i >> 9];
        d_start[i] = v;
        d_ptr[i] = v;
    }
}

__global__ void k_fill(const int* __restrict__ row, const int* __restrict__ col) {
    int e = blockIdx.x * blockDim.x + threadIdx.x;
    if (e < NE) {
        int c = col[e];
        int slot = atomicAdd(&d_ptr[c], 1);
        d_csr[slot] = row[e];
    }
}

// ---------------- node GEMM (f32x2 packed): g = dinv * (x @ W^T + b) ----------------
__global__ void k_gemm(const float* __restrict__ x, const float* __restrict__ W,
                       const float* __restrict__ b) {
    __shared__ __align__(16) float2 xs2[64 * 17];
    __shared__ __align__(16) float2 ws2[128 * 17];
    const int tid = threadIdx.x;
    const int tc = tid & 31;
    const int tr = tid >> 5;
    const int rb = blockIdx.x * 64;

    unsigned long long acc2[8][4];
#pragma unroll
    for (int i = 0; i < 8; i++)
#pragma unroll
        for (int j = 0; j < 4; j++) acc2[i][j] = 0ull;

    for (int kc = 0; kc < HF; kc += 32) {
#pragma unroll
        for (int l = 0; l < 2; l++) {
            int idx = tid + l * 256;
            int r = idx >> 3;
            int q = idx & 7;
            float4 v = make_float4(0.f, 0.f, 0.f, 0.f);
            if (rb + r < NN) v = *(const float4*)(x + (size_t)(rb + r) * HF + kc + q * 4);
            xs2[r * 17 + q * 2 + 0] = make_float2(v.x, v.y);
            xs2[r * 17 + q * 2 + 1] = make_float2(v.z, v.w);
        }
#pragma unroll
        for (int l = 0; l < 4; l++) {
            int idx = tid + l * 256;
            int t = idx >> 3;
            int q = idx & 7;
            float4 v = *(const float4*)(W + (size_t)t * HF + kc + q * 4);
            ws2[t * 17 + q * 2 + 0] = make_float2(v.x, v.y);
            ws2[t * 17 + q * 2 + 1] = make_float2(v.z, v.w);
        }
        __syncthreads();
#pragma unroll
        for (int kq = 0; kq < 16; kq++) {
            unsigned long long wv[4];
#pragma unroll
            for (int j = 0; j < 4; j++)
                wv[j] = *(const unsigned long long*)&ws2[(tc + 32 * j) * 17 + kq];
#pragma unroll
            for (int i = 0; i < 8; i++) {
                unsigned long long xv =
                    *(const unsigned long long*)&xs2[(tr * 8 + i) * 17 + kq];
#pragma unroll
                for (int j = 0; j < 4; j++) FFMA2(acc2[i][j], xv, wv[j]);
            }
        }
        __syncthreads();
    }

#pragma unroll
    for (int i = 0; i < 8; i++) {
        int r = rb + tr * 8 + i;
        if (r >= NN) break;
        float dv = d_dinv[r];
#pragma unroll
        for (int j = 0; j < 4; j++) {
            int c0 = tc + 32 * j;
            float lo, hi;
            asm("mov.b64 {%0, %1}, %2;" : "=f"(lo), "=f"(hi) : "l"(acc2[i][j]));
            d_g[(size_t)r * HF + c0] = dv * (lo + hi + b[c0]);
        }
    }
}

// ---------------- CSR aggregate: h[n] = dinv[n] * (g[n] + sum_{e: col=n} g[row_e]) ----------------
__global__ void k_aggr() {
    int gw = (blockIdx.x * blockDim.x + threadIdx.x) >> 5;
    if (gw >= NN) return;
    const int lane = threadIdx.x & 31;
    const int s = d_start[gw];
    const int cnt = d_cnt[gw];
    const float4* gp = (const float4*)d_g;

    float4 acc = __ldg(gp + (size_t)gw * 32 + lane);   // self loop
    for (int j0 = 0; j0 < cnt; j0 += 32) {
        int r = 0;
        if (j0 + lane < cnt) r = __ldg(d_csr + s + j0 + lane);
        int m = min(32, cnt - j0);
        int k = 0;
        for (; k + 4 <= m; k += 4) {
            int r0 = __shfl_sync(0xffffffffu, r, k + 0);
            int r1 = __shfl_sync(0xffffffffu, r, k + 1);
            int r2 = __shfl_sync(0xffffffffu, r, k + 2);
            int r3 = __shfl_sync(0xffffffffu, r, k + 3);
            float4 v0 = __ldg(gp + (size_t)r0 * 32 + lane);
            float4 v1 = __ldg(gp + (size_t)r1 * 32 + lane);
            float4 v2 = __ldg(gp + (size_t)r2 * 32 + lane);
            float4 v3 = __ldg(gp + (size_t)r3 * 32 + lane);
            acc.x += v0.x + v1.x + v2.x + v3.x;
            acc.y += v0.y + v1.y + v2.y + v3.y;
            acc.z += v0.z + v1.z + v2.z + v3.z;
            acc.w += v0.w + v1.w + v2.w + v3.w;
        }
        for (; k < m; k++) {
            int rr = __shfl_sync(0xffffffffu, r, k);
            float4 v = __ldg(gp + (size_t)rr * 32 + lane);
            acc.x += v.x; acc.y += v.y; acc.z += v.z; acc.w += v.w;
        }
    }
    float dv = d_dinv[gw];
    acc.x *= dv; acc.y *= dv; acc.z *= dv; acc.w *= dv;
    ((float4*)d_h)[(size_t)gw * 32 + lane] = acc;
}

// ---------------- per-node projection: pr[n] = Wr@h2[n]+bfc, pc[n] = Wc@h2[n] ----------------
// Wfc is [NC][2*HF]; Wr = Wfc[:, :HF], Wc = Wfc[:, HF:]. One thread per node;
// single pass over h2[n] feeds both projections (f32x2 packed).
__global__ void k_proj(const float* __restrict__ Wfc, const float* __restrict__ bfc) {
    __shared__ __align__(16) float ws[NC * 256];
    __shared__ float bs[NC];
    const int tid = threadIdx.x;
    for (int i = tid; i < NC * 256; i += 128) ws[i] = Wfc[i];
    if (tid < NC) bs[tid] = bfc[tid];
    __syncthreads();

    const int n = blockIdx.x * 128 + tid;
    if (n >= NN) return;

    unsigned long long ar[NC], ac[NC];
#pragma unroll
    for (int c = 0; c < NC; c++) { ar[c] = 0ull; ac[c] = 0ull; }

    const ulonglong2* hp = (const ulonglong2*)(d_h + (size_t)n * HF);
#pragma unroll
    for (int q = 0; q < 32; q++) {
        ulonglong2 xv = __ldg(hp + q);
#pragma unroll
        for (int c = 0; c < NC; c++) {
            ulonglong2 wr = *(const ulonglong2*)&ws[c * 256 + q * 4];
            ulonglong2 wc = *(const ulonglong2*)&ws[c * 256 + 128 + q * 4];
            FFMA2(ar[c], xv.x, wr.x);
            FFMA2(ar[c], xv.y, wr.y);
            FFMA2(ac[c], xv.x, wc.x);
            FFMA2(ac[c], xv.y, wc.y);
        }
    }

    float outr[PSTR], outc[PSTR];
#pragma unroll
    for (int c = 0; c < NC; c++) {
        float lo, hi;
        asm("mov.b64 {%0, %1}, %2;" : "=f"(lo), "=f"(hi) : "l"(ar[c]));
        outr[c] = lo + hi + bs[c];
        asm("mov.b64 {%0, %1}, %2;" : "=f"(lo), "=f"(hi) : "l"(ac[c]));
        outc[c] = lo + hi;
    }
    outr[10] = 0.f; outr[11] = 0.f;
    outc[10] = 0.f; outc[11] = 0.f;

    float4* prp = (float4*)(d_pr + (size_t)n * PSTR);
    float4* pcp = (float4*)(d_pc + (size_t)n * PSTR);
#pragma unroll
    for (int j = 0; j < 3; j++) {
        prp[j] = *(const float4*)&outr[j * 4];
        pcp[j] = *(const float4*)&outc[j * 4];
    }
}

// ---------------- edge head: logits[e] = pr[row_e] + pc[col_e]; softmax + loss ----------------
__global__ void k_edge_head(const int* __restrict__ row, const int* __restrict__ col,
                            const int* __restrict__ label, float* __restrict__ logits) {
    __shared__ float red[256];
    const int tid = threadIdx.x;
    const int e = blockIdx.x * 256 + tid;
    float myloss = 0.f;
    if (e < NE) {
        int r = row[e], c = col[e];
        const float4* prp = (const float4*)(d_pr + (size_t)r * PSTR);
        const float4* pcp = (const float4*)(d_pc + (size_t)c * PSTR);
        float acc[PSTR];
#pragma unroll
        for (int j = 0; j < 3; j++) {
            float4 a = __ldg(prp + j);
            float4 b = __ldg(pcp + j);
            acc[j * 4 + 0] = a.x + b.x;
            acc[j * 4 + 1] = a.y + b.y;
            acc[j * 4 + 2] = a.z + b.z;
            acc[j * 4 + 3] = a.w + b.w;
        }
        float m = acc[0];
#pragma unroll
        for (int cc = 1; cc < NC; cc++) m = fmaxf(m, acc[cc]);
        float s = 0.f;
#pragma unroll
        for (int cc = 0; cc < NC; cc++) s += expf(acc[cc] - m);
        float lse = m + logf(s);
        myloss = lse - acc[label[e]];
        float* lp = logits + (size_t)e * NC;
#pragma unroll
        for (int cc = 0; cc < NC; cc++) lp[cc] = acc[cc];
    }
    red[tid] = myloss;
    __syncthreads();
    for (int s2 = 128; s2 > 0; s2 >>= 1) {
        if (tid < s2) red[tid] += red[tid + s2];
        __syncthreads();
    }
    if (tid == 0) atomicAdd(&d_loss, red[0]);
}

__global__ void k_final(float* __restrict__ loss_out) {
    if (loss_out) loss_out[0] = d_loss * (1.0f / (float)NE);
}

// ---------------- launch ----------------
extern "C" void kernel_launch(void* const* d_in, const int* in_sizes, int n_in,
                              void* d_out, int out_size) {
    const float* feat = (const float*)d_in[0];
    const float* W1   = (const float*)d_in[1];
    const float* b1   = (const float*)d_in[2];
    const float* W2   = (const float*)d_in[3];
    const float* b2   = (const float*)d_in[4];
    const float* Wfc  = (const float*)d_in[5];
    const float* bfc  = (const float*)d_in[6];
    const int*   row  = (const int*)d_in[7];
    const int*   col  = (const int*)d_in[8];
    const int*   lab  = (const int*)d_in[9];

    float* out = (float*)d_out;
    float* lossp;
    float* logits;
    if (out_size == NE * NC + 1) { lossp = out; logits = out + 1; }
    else                         { lossp = nullptr; logits = out; }

    void* ph = nullptr;
    cudaGetSymbolAddress(&ph, d_h);
    const float* h1 = (const float*)ph;

    const int TB = 256;
    const int nb_nodes = (NN + TB - 1) / TB;
    const int nb_edges = (NE + TB - 1) / TB;
    const int nb_gemm  = (NN + 63) / 64;
    const int nb_aggr  = (NN * 32 + TB - 1) / TB;
    const int nb_proj  = (NN + 127) / 128;

    k_init<<<nb_nodes, TB>>>();
    k_hist<<<nb_edges, TB>>>(row, col);
    k_dinv<<<nb_nodes, TB>>>();
    k_scan1<<<NBLK, 256>>>();
    k_scan2<<<1, 32>>>();
    k_scan3<<<nb_nodes, TB>>>();
    k_fill<<<nb_edges, TB>>>(row, col);

    // conv 1
    k_gemm<<<nb_gemm, TB>>>(feat, W1, b1);
    k_aggr<<<nb_aggr, TB>>>();            // -> d_h = h1

    // conv 2
    k_gemm<<<nb_gemm, TB>>>(h1, W2, b2);
    k_aggr<<<nb_aggr, TB>>>();            // -> d_h = h2

    // edge head: per-node projection, then per-edge add + softmax
    k_proj<<<nb_proj, 128>>>(Wfc, bfc);
    k_edge_head<<<nb_edges, TB>>>(row, col, lab, logits);
    k_final<<<1, 1>>>(lossp);
}

// round 12
// speedup vs baseline: 1.7228x; 1.0911x over previous
#include <cuda_runtime.h>
#include <cstdint>

#define NN 50000
#define NE 600000
#define HF 128
#define NC 10
#define PSTR 12                  // padded projection row stride (floats)
#define NBLK ((NN + 511) / 512)  // 98 scan blocks

// ---------------- scratch (static device globals; no allocation) ----------------
__device__ __align__(16) float d_g[(size_t)NN * HF];    // dinv*(xW^T+b)
__device__ __align__(16) float d_h[(size_t)NN * HF];    // conv output (h1 then h2)
__device__ __align__(16) float d_pr[(size_t)NN * PSTR]; // Wr@h2[n] + bfc
__device__ __align__(16) float d_pc[(size_t)NN * PSTR]; // Wc@h2[n]
__device__ int   d_deg[NN];      // row-degree + 1 (norm)
__device__ float d_dinv[NN];
__device__ int   d_cnt[NN];      // col histogram (CSR)
__device__ int   d_start[NN];    // CSR offsets
__device__ int   d_ptr[NN];      // CSR fill cursors
__device__ int   d_csr[NE];      // source row per CSR slot
__device__ int   d_bsum[128];    // scan block sums
__device__ int   d_boff[128];    // scan block offsets
__device__ float d_loss;

#define FFMA2(acc, a, b) asm("fma.rn.f32x2 %0, %1, %2, %0;" : "+l"(acc) : "l"(a), "l"(b))

// ---------------- init ----------------
__global__ void k_init() {
    int i = blockIdx.x * blockDim.x + threadIdx.x;
    if (i < NN) { d_deg[i] = 1; d_cnt[i] = 0; }
    if (i == 0) d_loss = 0.f;
}

// row-degree (norm) + col histogram (CSR) in one pass
__global__ void k_hist(const int* __restrict__ row, const int* __restrict__ col) {
    int e = blockIdx.x * blockDim.x + threadIdx.x;
    if (e < NE) {
        atomicAdd(&d_deg[row[e]], 1);
        atomicAdd(&d_cnt[col[e]], 1);
    }
}

__global__ void k_dinv() {
    int i = blockIdx.x * blockDim.x + threadIdx.x;
    if (i < NN) d_dinv[i] = rsqrtf((float)d_deg[i]);
}

// ---------------- multi-block exclusive scan of d_cnt ----------------
__global__ void k_scan1() {
    __shared__ int wsum[8];
    const int t = threadIdx.x;
    const int base = blockIdx.x * 512 + t * 2;
    int c0 = (base < NN) ? d_cnt[base] : 0;
    int c1 = (base + 1 < NN) ? d_cnt[base + 1] : 0;
    int s = c0 + c1;
    int v = s;
#pragma unroll
    for (int o = 1; o < 32; o <<= 1) {
        int u = __shfl_up_sync(0xffffffffu, v, o);
        if ((t & 31) >= o) v += u;
    }
    if ((t & 31) == 31) wsum[t >> 5] = v;
    __syncthreads();
    if (t < 8) {
        int w = wsum[t];
#pragma unroll
        for (int o = 1; o < 8; o <<= 1) {
            int u = __shfl_up_sync(0xffu, w, o);
            if (t >= o) w += u;
        }
        wsum[t] = w;
    }
    __syncthreads();
    int pre = v - s + ((t >= 32) ? wsum[(t >> 5) - 1] : 0);
    if (base < NN) d_start[base] = pre;
    if (base + 1 < NN) d_start[base + 1] = pre + c0;
    if (t == 255) d_bsum[blockIdx.x] = wsum[7];
}

__global__ void k_scan2() {
    const int l = threadIdx.x;
    int c[4];
    int s = 0;
#pragma unroll
    for (int i = 0; i < 4; i++) {
        int idx = l * 4 + i;
        c[i] = (idx < NBLK) ? d_bsum[idx] : 0;
        s += c[i];
    }
    int v = s;
#pragma unroll
    for (int o = 1; o < 32; o <<= 1) {
        int u = __shfl_up_sync(0xffffffffu, v, o);
        if (l >= o) v += u;
    }
    int ex = v - s;
#pragma unroll
    for (int i = 0; i < 4; i++) {
        int idx = l * 4 + i;
        if (idx < NBLK) d_boff[idx] = ex;
        ex += c[i];
    }
}

__global__ void k_scan3() {
    int i = blockIdx.x * blockDim.x + threadIdx.x;
    if (i < NN) {
        int v = d_start[i] + d_boff[i >> 9];
        d_start[i] = v;
        d_ptr[i] = v;
    }
}

__global__ void k_fill(const int* __restrict__ row, const int* __restrict__ col) {
    int e = blockIdx.x * blockDim.x + threadIdx.x;
    if (e < NE) {
        int c = col[e];
        int slot = atomicAdd(&d_ptr[c], 1);
        d_csr[slot] = row[e];
    }
}

// ---------------- node GEMM (f32x2 packed): g = dinv * (x @ W^T + b) ----------------
__global__ void k_gemm(const float* __restrict__ x, const float* __restrict__ W,
                       const float* __restrict__ b) {
    __shared__ __align__(16) float2 xs2[64 * 17];
    __shared__ __align__(16) float2 ws2[128 * 17];
    const int tid = threadIdx.x;
    const int tc = tid & 31;
    const int tr = tid >> 5;
    const int rb = blockIdx.x * 64;

    unsigned long long acc2[8][4];
#pragma unroll
    for (int i = 0; i < 8; i++)
#pragma unroll
        for (int j = 0; j < 4; j++) acc2[i][j] = 0ull;

    for (int kc = 0; kc < HF; kc += 32) {
#pragma unroll
        for (int l = 0; l < 2; l++) {
            int idx = tid + l * 256;
            int r = idx >> 3;
            int q = idx & 7;
            float4 v = make_float4(0.f, 0.f, 0.f, 0.f);
            if (rb + r < NN) v = *(const float4*)(x + (size_t)(rb + r) * HF + kc + q * 4);
            xs2[r * 17 + q * 2 + 0] = make_float2(v.x, v.y);
            xs2[r * 17 + q * 2 + 1] = make_float2(v.z, v.w);
        }
#pragma unroll
        for (int l = 0; l < 4; l++) {
            int idx = tid + l * 256;
            int t = idx >> 3;
            int q = idx & 7;
            float4 v = *(const float4*)(W + (size_t)t * HF + kc + q * 4);
            ws2[t * 17 + q * 2 + 0] = make_float2(v.x, v.y);
            ws2[t * 17 + q * 2 + 1] = make_float2(v.z, v.w);
        }
        __syncthreads();
#pragma unroll
        for (int kq = 0; kq < 16; kq++) {
            unsigned long long wv[4];
#pragma unroll
            for (int j = 0; j < 4; j++)
                wv[j] = *(const unsigned long long*)&ws2[(tc + 32 * j) * 17 + kq];
#pragma unroll
            for (int i = 0; i < 8; i++) {
                unsigned long long xv =
                    *(const unsigned long long*)&xs2[(tr * 8 + i) * 17 + kq];
#pragma unroll
                for (int j = 0; j < 4; j++) FFMA2(acc2[i][j], xv, wv[j]);
            }
        }
        __syncthreads();
    }

#pragma unroll
    for (int i = 0; i < 8; i++) {
        int r = rb + tr * 8 + i;
        if (r >= NN) break;
        float dv = d_dinv[r];
#pragma unroll
        for (int j = 0; j < 4; j++) {
            int c0 = tc + 32 * j;
            float lo, hi;
            asm("mov.b64 {%0, %1}, %2;" : "=f"(lo), "=f"(hi) : "l"(acc2[i][j]));
            d_g[(size_t)r * HF + c0] = dv * (lo + hi + b[c0]);
        }
    }
}

// ---------------- CSR aggregate: h[n] = dinv[n] * (g[n] + sum_{e: col=n} g[row_e]) ----------------
__global__ void k_aggr() {
    int gw = (blockIdx.x * blockDim.x + threadIdx.x) >> 5;
    if (gw >= NN) return;
    const int lane = threadIdx.x & 31;
    const int s = d_start[gw];
    const int cnt = d_cnt[gw];
    const float4* gp = (const float4*)d_g;

    float4 acc = __ldg(gp + (size_t)gw * 32 + lane);   // self loop
    for (int j0 = 0; j0 < cnt; j0 += 32) {
        int r = 0;
        if (j0 + lane < cnt) r = __ldg(d_csr + s + j0 + lane);
        int m = min(32, cnt - j0);
        int k = 0;
        for (; k + 4 <= m; k += 4) {
            int r0 = __shfl_sync(0xffffffffu, r, k + 0);
            int r1 = __shfl_sync(0xffffffffu, r, k + 1);
            int r2 = __shfl_sync(0xffffffffu, r, k + 2);
            int r3 = __shfl_sync(0xffffffffu, r, k + 3);
            float4 v0 = __ldg(gp + (size_t)r0 * 32 + lane);
            float4 v1 = __ldg(gp + (size_t)r1 * 32 + lane);
            float4 v2 = __ldg(gp + (size_t)r2 * 32 + lane);
            float4 v3 = __ldg(gp + (size_t)r3 * 32 + lane);
            acc.x += v0.x + v1.x + v2.x + v3.x;
            acc.y += v0.y + v1.y + v2.y + v3.y;
            acc.z += v0.z + v1.z + v2.z + v3.z;
            acc.w += v0.w + v1.w + v2.w + v3.w;
        }
        for (; k < m; k++) {
            int rr = __shfl_sync(0xffffffffu, r, k);
            float4 v = __ldg(gp + (size_t)rr * 32 + lane);
            acc.x += v.x; acc.y += v.y; acc.z += v.z; acc.w += v.w;
        }
    }
    float dv = d_dinv[gw];
    acc.x *= dv; acc.y *= dv; acc.z *= dv; acc.w *= dv;
    ((float4*)d_h)[(size_t)gw * 32 + lane] = acc;
}

// ---------------- per-node projection: pr[n] = Wr@h2[n]+bfc, pc[n] = Wc@h2[n] ----------------
__global__ void k_proj(const float* __restrict__ Wfc, const float* __restrict__ bfc) {
    __shared__ __align__(16) float ws[NC * 256];
    __shared__ float bs[NC];
    const int tid = threadIdx.x;
    for (int i = tid; i < NC * 256; i += 128) ws[i] = Wfc[i];
    if (tid < NC) bs[tid] = bfc[tid];
    __syncthreads();

    const int n = blockIdx.x * 128 + tid;
    if (n >= NN) return;

    unsigned long long ar[NC], ac[NC];
#pragma unroll
    for (int c = 0; c < NC; c++) { ar[c] = 0ull; ac[c] = 0ull; }

    const ulonglong2* hp = (const ulonglong2*)(d_h + (size_t)n * HF);
#pragma unroll
    for (int q = 0; q < 32; q++) {
        ulonglong2 xv = __ldg(hp + q);
#pragma unroll
        for (int c = 0; c < NC; c++) {
            ulonglong2 wr = *(const ulonglong2*)&ws[c * 256 + q * 4];
            ulonglong2 wc = *(const ulonglong2*)&ws[c * 256 + 128 + q * 4];
            FFMA2(ar[c], xv.x, wr.x);
            FFMA2(ar[c], xv.y, wr.y);
            FFMA2(ac[c], xv.x, wc.x);
            FFMA2(ac[c], xv.y, wc.y);
        }
    }

    float outr[PSTR], outc[PSTR];
#pragma unroll
    for (int c = 0; c < NC; c++) {
        float lo, hi;
        asm("mov.b64 {%0, %1}, %2;" : "=f"(lo), "=f"(hi) : "l"(ar[c]));
        outr[c] = lo + hi + bs[c];
        asm("mov.b64 {%0, %1}, %2;" : "=f"(lo), "=f"(hi) : "l"(ac[c]));
        outc[c] = lo + hi;
    }
    outr[10] = 0.f; outr[11] = 0.f;
    outc[10] = 0.f; outc[11] = 0.f;

    float4* prp = (float4*)(d_pr + (size_t)n * PSTR);
    float4* pcp = (float4*)(d_pc + (size_t)n * PSTR);
#pragma unroll
    for (int j = 0; j < 3; j++) {
        prp[j] = *(const float4*)&outr[j * 4];
        pcp[j] = *(const float4*)&outc[j * 4];
    }
}

// ---------------- edge head: logits[e] = pr[row_e] + pc[col_e]; softmax + loss ----------------
__global__ void k_edge_head(const int* __restrict__ row, const int* __restrict__ col,
                            const int* __restrict__ label, float* __restrict__ logits) {
    __shared__ float red[256];
    const int tid = threadIdx.x;
    const int e = blockIdx.x * 256 + tid;
    float myloss = 0.f;
    if (e < NE) {
        int r = row[e], c = col[e];
        const float4* prp = (const float4*)(d_pr + (size_t)r * PSTR);
        const float4* pcp = (const float4*)(d_pc + (size_t)c * PSTR);
        float acc[PSTR];
#pragma unroll
        for (int j = 0; j < 3; j++) {
            float4 a = __ldg(prp + j);
            float4 b = __ldg(pcp + j);
            acc[j * 4 + 0] = a.x + b.x;
            acc[j * 4 + 1] = a.y + b.y;
            acc[j * 4 + 2] = a.z + b.z;
            acc[j * 4 + 3] = a.w + b.w;
        }
        float m = acc[0];
#pragma unroll
        for (int cc = 1; cc < NC; cc++) m = fmaxf(m, acc[cc]);
        float s = 0.f;
#pragma unroll
        for (int cc = 0; cc < NC; cc++) s += expf(acc[cc] - m);
        float lse = m + logf(s);
        myloss = lse - acc[label[e]];
        float* lp = logits + (size_t)e * NC;
#pragma unroll
        for (int cc = 0; cc < NC; cc++) lp[cc] = acc[cc];
    }
    red[tid] = myloss;
    __syncthreads();
    for (int s2 = 128; s2 > 0; s2 >>= 1) {
        if (tid < s2) red[tid] += red[tid + s2];
        __syncthreads();
    }
    if (tid == 0) atomicAdd(&d_loss, red[0]);
}

__global__ void k_final(float* __restrict__ loss_out) {
    if (loss_out) loss_out[0] = d_loss * (1.0f / (float)NE);
}

// ---------------- launch ----------------
extern "C" void kernel_launch(void* const* d_in, const int* in_sizes, int n_in,
                              void* d_out, int out_size) {
    const float* feat = (const float*)d_in[0];
    const float* W1   = (const float*)d_in[1];
    const float* b1   = (const float*)d_in[2];
    const float* W2   = (const float*)d_in[3];
    const float* b2   = (const float*)d_in[4];
    const float* Wfc  = (const float*)d_in[5];
    const float* bfc  = (const float*)d_in[6];
    const int*   row  = (const int*)d_in[7];
    const int*   col  = (const int*)d_in[8];
    const int*   lab  = (const int*)d_in[9];

    float* out = (float*)d_out;
    float* lossp;
    float* logits;
    if (out_size == NE * NC + 1) { lossp = out; logits = out + 1; }
    else                         { lossp = nullptr; logits = out; }

    void* ph = nullptr;
    cudaGetSymbolAddress(&ph, d_h);
    const float* h1 = (const float*)ph;

    // One-time side-stream/event setup (host-side resources only; no device mem).
    // Same GPU work is issued on every call — only the resources are reused.
    static cudaStream_t s_side = nullptr;
    static cudaEvent_t  evA = nullptr, evB = nullptr;
    if (s_side == nullptr) {
        cudaStreamCreateWithFlags(&s_side, cudaStreamNonBlocking);
        cudaEventCreateWithFlags(&evA, cudaEventDisableTiming);
        cudaEventCreateWithFlags(&evB, cudaEventDisableTiming);
    }

    const int TB = 256;
    const int nb_nodes = (NN + TB - 1) / TB;
    const int nb_edges = (NE + TB - 1) / TB;
    const int nb_gemm  = (NN + 63) / 64;
    const int nb_aggr  = (NN * 32 + TB - 1) / TB;
    const int nb_proj  = (NN + 127) / 128;

    // main stream: init -> hist -> dinv -> gemm1 (gemm1 at launch index 3 for ncu)
    k_init<<<nb_nodes, TB>>>();
    k_hist<<<nb_edges, TB>>>(row, col);
    cudaEventRecord(evA, 0);              // fork point: hist complete
    k_dinv<<<nb_nodes, TB>>>();
    k_gemm<<<nb_gemm, TB>>>(feat, W1, b1);

    // side stream: CSR build (depends only on hist), overlaps gemm1
    cudaStreamWaitEvent(s_side, evA, 0);
    k_scan1<<<NBLK, 256, 0, s_side>>>();
    k_scan2<<<1, 32, 0, s_side>>>();
    k_scan3<<<nb_nodes, TB, 0, s_side>>>();
    k_fill<<<nb_edges, TB, 0, s_side>>>(row, col);
    cudaEventRecord(evB, s_side);

    // join: aggr needs CSR + g
    cudaStreamWaitEvent(0, evB, 0);
    k_aggr<<<nb_aggr, TB>>>();            // -> d_h = h1

    // conv 2
    k_gemm<<<nb_gemm, TB>>>(h1, W2, b2);
    k_aggr<<<nb_aggr, TB>>>();            // -> d_h = h2

    // edge head: per-node projection, then per-edge add + softmax
    k_proj<<<nb_proj, 128>>>(Wfc, bfc);
    k_edge_head<<<nb_edges, TB>>>(row, col, lab, logits);
    k_final<<<1, 1>>>(lossp);
}

// round 14
// speedup vs baseline: 1.7594x; 1.0213x over previous
#include <cuda_runtime.h>
#include <cstdint>

#define NN 50000
#define NE 600000
#define HF 128
#define NC 10
#define PSTR 12                  // padded projection row stride (floats)
#define NBLK ((NN + 511) / 512)  // 98 scan blocks

// ---------------- scratch (static device globals; no allocation) ----------------
__device__ __align__(16) float d_g[(size_t)NN * HF];    // lin = xW^T + b (UNscaled)
__device__ __align__(16) float d_h[(size_t)NN * HF];    // conv output (h1 then h2)
__device__ __align__(16) float d_pr[(size_t)NN * PSTR]; // Wr@h2[n] + bfc
__device__ __align__(16) float d_pc[(size_t)NN * PSTR]; // Wc@h2[n]
__device__ int   d_deg[NN];      // row-degree + 1 (norm)
__device__ float d_dinv[NN];
__device__ int   d_cnt[NN];      // col histogram (CSR)
__device__ int   d_start[NN];    // CSR offsets
__device__ int   d_ptr[NN];      // CSR fill cursors
__device__ int   d_csr[NE];      // source row per CSR slot
__device__ int   d_bsum[128];    // scan block sums
__device__ int   d_boff[128];    // scan block offsets
__device__ float d_loss;

#define FFMA2(acc, a, b) asm("fma.rn.f32x2 %0, %1, %2, %0;" : "+l"(acc) : "l"(a), "l"(b))

// ---------------- init ----------------
__global__ void k_init() {
    int i = blockIdx.x * blockDim.x + threadIdx.x;
    if (i < NN) { d_deg[i] = 1; d_cnt[i] = 0; }
    if (i == 0) d_loss = 0.f;
}

// row-degree (norm) + col histogram (CSR) in one pass
__global__ void k_hist(const int* __restrict__ row, const int* __restrict__ col) {
    int e = blockIdx.x * blockDim.x + threadIdx.x;
    if (e < NE) {
        atomicAdd(&d_deg[row[e]], 1);
        atomicAdd(&d_cnt[col[e]], 1);
    }
}

__global__ void k_dinv() {
    int i = blockIdx.x * blockDim.x + threadIdx.x;
    if (i < NN) d_dinv[i] = rsqrtf((float)d_deg[i]);
}

// ---------------- multi-block exclusive scan of d_cnt ----------------
__global__ void k_scan1() {
    __shared__ int wsum[8];
    const int t = threadIdx.x;
    const int base = blockIdx.x * 512 + t * 2;
    int c0 = (base < NN) ? d_cnt[base] : 0;
    int c1 = (base + 1 < NN) ? d_cnt[base + 1] : 0;
    int s = c0 + c1;
    int v = s;
#pragma unroll
    for (int o = 1; o < 32; o <<= 1) {
        int u = __shfl_up_sync(0xffffffffu, v, o);
        if ((t & 31) >= o) v += u;
    }
    if ((t & 31) == 31) wsum[t >> 5] = v;
    __syncthreads();
    if (t < 8) {
        int w = wsum[t];
#pragma unroll
        for (int o = 1; o < 8; o <<= 1) {
            int u = __shfl_up_sync(0xffu, w, o);
            if (t >= o) w += u;
        }
        wsum[t] = w;
    }
    __syncthreads();
    int pre = v - s + ((t >= 32) ? wsum[(t >> 5) - 1] : 0);
    if (base < NN) d_start[base] = pre;
    if (base + 1 < NN) d_start[base + 1] = pre + c0;
    if (t == 255) d_bsum[blockIdx.x] = wsum[7];
}

__global__ void k_scan2() {
    const int l = threadIdx.x;
    int c[4];
    int s = 0;
#pragma unroll
    for (int i = 0; i < 4; i++) {
        int idx = l * 4 + i;
        c[i] = (idx < NBLK) ? d_bsum[idx] : 0;
        s += c[i];
    }
    int v = s;
#pragma unroll
    for (int o = 1; o < 32; o <<= 1) {
        int u = __shfl_up_sync(0xffffffffu, v, o);
        if (l >= o) v += u;
    }
    int ex = v - s;
#pragma unroll
    for (int i = 0; i < 4; i++) {
        int idx = l * 4 + i;
        if (idx < NBLK) d_boff[idx] = ex;
        ex += c[i];
    }
}

__global__ void k_scan3() {
    int i = blockIdx.x * blockDim.x + threadIdx.x;
    if (i < NN) {
        int v = d_start[i] + d_boff[i >> 9];
        d_start[i] = v;
        d_ptr[i] = v;
    }
}

__global__ void k_fill(const int* __restrict__ row, const int* __restrict__ col) {
    int e = blockIdx.x * blockDim.x + threadIdx.x;
    if (e < NE) {
        int c = col[e];
        int slot = atomicAdd(&d_ptr[c], 1);
        d_csr[slot] = row[e];
    }
}

// ---------------- node GEMM (f32x2 packed): g = x @ W^T + b (no dinv; applied in aggr) ----------------
__global__ void __launch_bounds__(256, 2)
k_gemm(const float* __restrict__ x, const float* __restrict__ W,
       const float* __restrict__ b) {
    __shared__ __align__(16) float2 xs2[64 * 17];
    __shared__ __align__(16) float2 ws2[128 * 17];
    const int tid = threadIdx.x;
    const int tc = tid & 31;
    const int tr = tid >> 5;
    const int rb = blockIdx.x * 64;

    unsigned long long acc2[8][4];
#pragma unroll
    for (int i = 0; i < 8; i++)
#pragma unroll
        for (int j = 0; j < 4; j++) acc2[i][j] = 0ull;

    for (int kc = 0; kc < HF; kc += 32) {
#pragma unroll
        for (int l = 0; l < 2; l++) {
            int idx = tid + l * 256;
            int r = idx >> 3;
            int q = idx & 7;
            float4 v = make_float4(0.f, 0.f, 0.f, 0.f);
            if (rb + r < NN) v = *(const float4*)(x + (size_t)(rb + r) * HF + kc + q * 4);
            xs2[r * 17 + q * 2 + 0] = make_float2(v.x, v.y);
            xs2[r * 17 + q * 2 + 1] = make_float2(v.z, v.w);
        }
#pragma unroll
        for (int l = 0; l < 4; l++) {
            int idx = tid + l * 256;
            int t = idx >> 3;
            int q = idx & 7;
            float4 v = *(const float4*)(W + (size_t)t * HF + kc + q * 4);
            ws2[t * 17 + q * 2 + 0] = make_float2(v.x, v.y);
            ws2[t * 17 + q * 2 + 1] = make_float2(v.z, v.w);
        }
        __syncthreads();
#pragma unroll
        for (int kq = 0; kq < 16; kq++) {
            unsigned long long wv[4];
#pragma unroll
            for (int j = 0; j < 4; j++)
                wv[j] = *(const unsigned long long*)&ws2[(tc + 32 * j) * 17 + kq];
#pragma unroll
            for (int i = 0; i < 8; i++) {
                unsigned long long xv =
                    *(const unsigned long long*)&xs2[(tr * 8 + i) * 17 + kq];
#pragma unroll
                for (int j = 0; j < 4; j++) FFMA2(acc2[i][j], xv, wv[j]);
            }
        }
        __syncthreads();
    }

#pragma unroll
    for (int i = 0; i < 8; i++) {
        int r = rb + tr * 8 + i;
        if (r >= NN) break;
#pragma unroll
        for (int j = 0; j < 4; j++) {
            int c0 = tc + 32 * j;
            float lo, hi;
            asm("mov.b64 {%0, %1}, %2;" : "=f"(lo), "=f"(hi) : "l"(acc2[i][j]));
            d_g[(size_t)r * HF + c0] = lo + hi + b[c0];
        }
    }
}

// ---------------- CSR aggregate: h[n] = dinv[n]*(dinv[n]*lin[n] + sum_e dinv[r]*lin[r]) ----------------
__global__ void k_aggr() {
    int gw = (blockIdx.x * blockDim.x + threadIdx.x) >> 5;
    if (gw >= NN) return;
    const int lane = threadIdx.x & 31;
    const int s = d_start[gw];
    const int cnt = d_cnt[gw];
    const float4* gp = (const float4*)d_g;
    const float dv = d_dinv[gw];

    float4 sv = __ldg(gp + (size_t)gw * 32 + lane);   // self loop (lin)
    float4 acc;
    acc.x = dv * sv.x; acc.y = dv * sv.y; acc.z = dv * sv.z; acc.w = dv * sv.w;

    for (int j0 = 0; j0 < cnt; j0 += 32) {
        int r = 0;
        float dvl = 0.f;
        if (j0 + lane < cnt) {
            r = __ldg(d_csr + s + j0 + lane);
            dvl = __ldg(d_dinv + r);
        }
        int m = min(32, cnt - j0);
        int k = 0;
        for (; k + 4 <= m; k += 4) {
            int r0 = __shfl_sync(0xffffffffu, r, k + 0);
            int r1 = __shfl_sync(0xffffffffu, r, k + 1);
            int r2 = __shfl_sync(0xffffffffu, r, k + 2);
            int r3 = __shfl_sync(0xffffffffu, r, k + 3);
            float w0 = __shfl_sync(0xffffffffu, dvl, k + 0);
            float w1 = __shfl_sync(0xffffffffu, dvl, k + 1);
            float w2 = __shfl_sync(0xffffffffu, dvl, k + 2);
            float w3 = __shfl_sync(0xffffffffu, dvl, k + 3);
            float4 v0 = __ldg(gp + (size_t)r0 * 32 + lane);
            float4 v1 = __ldg(gp + (size_t)r1 * 32 + lane);
            float4 v2 = __ldg(gp + (size_t)r2 * 32 + lane);
            float4 v3 = __ldg(gp + (size_t)r3 * 32 + lane);
            acc.x = fmaf(w0, v0.x, fmaf(w1, v1.x, fmaf(w2, v2.x, fmaf(w3, v3.x, acc.x))));
            acc.y = fmaf(w0, v0.y, fmaf(w1, v1.y, fmaf(w2, v2.y, fmaf(w3, v3.y, acc.y))));
            acc.z = fmaf(w0, v0.z, fmaf(w1, v1.z, fmaf(w2, v2.z, fmaf(w3, v3.z, acc.z))));
            acc.w = fmaf(w0, v0.w, fmaf(w1, v1.w, fmaf(w2, v2.w, fmaf(w3, v3.w, acc.w))));
        }
        for (; k < m; k++) {
            int rr = __shfl_sync(0xffffffffu, r, k);
            float ww = __shfl_sync(0xffffffffu, dvl, k);
            float4 v = __ldg(gp + (size_t)rr * 32 + lane);
            acc.x = fmaf(ww, v.x, acc.x);
            acc.y = fmaf(ww, v.y, acc.y);
            acc.z = fmaf(ww, v.z, acc.z);
            acc.w = fmaf(ww, v.w, acc.w);
        }
    }
    acc.x *= dv; acc.y *= dv; acc.z *= dv; acc.w *= dv;
    ((float4*)d_h)[(size_t)gw * 32 + lane] = acc;
}

// ---------------- per-node projection: pr[n] = Wr@h2[n]+bfc, pc[n] = Wc@h2[n] ----------------
__global__ void k_proj(const float* __restrict__ Wfc, const float* __restrict__ bfc) {
    __shared__ __align__(16) float ws[NC * 256];
    __shared__ float bs[NC];
    const int tid = threadIdx.x;
    for (int i = tid; i < NC * 256; i += 128) ws[i] = Wfc[i];
    if (tid < NC) bs[tid] = bfc[tid];
    __syncthreads();

    const int n = blockIdx.x * 128 + tid;
    if (n >= NN) return;

    unsigned long long ar[NC], ac[NC];
#pragma unroll
    for (int c = 0; c < NC; c++) { ar[c] = 0ull; ac[c] = 0ull; }

    const ulonglong2* hp = (const ulonglong2*)(d_h + (size_t)n * HF);
#pragma unroll
    for (int q = 0; q < 32; q++) {
        ulonglong2 xv = __ldg(hp + q);
#pragma unroll
        for (int c = 0; c < NC; c++) {
            ulonglong2 wr = *(const ulonglong2*)&ws[c * 256 + q * 4];
            ulonglong2 wc = *(const ulonglong2*)&ws[c * 256 + 128 + q * 4];
            FFMA2(ar[c], xv.x, wr.x);
            FFMA2(ar[c], xv.y, wr.y);
            FFMA2(ac[c], xv.x, wc.x);
            FFMA2(ac[c], xv.y, wc.y);
        }
    }

    float outr[PSTR], outc[PSTR];
#pragma unroll
    for (int c = 0; c < NC; c++) {
        float lo, hi;
        asm("mov.b64 {%0, %1}, %2;" : "=f"(lo), "=f"(hi) : "l"(ar[c]));
        outr[c] = lo + hi + bs[c];
        asm("mov.b64 {%0, %1}, %2;" : "=f"(lo), "=f"(hi) : "l"(ac[c]));
        outc[c] = lo + hi;
    }
    outr[10] = 0.f; outr[11] = 0.f;
    outc[10] = 0.f; outc[11] = 0.f;

    float4* prp = (float4*)(d_pr + (size_t)n * PSTR);
    float4* pcp = (float4*)(d_pc + (size_t)n * PSTR);
#pragma unroll
    for (int j = 0; j < 3; j++) {
        prp[j] = *(const float4*)&outr[j * 4];
        pcp[j] = *(const float4*)&outc[j * 4];
    }
}

// ---------------- edge head: logits[e] = pr[row_e] + pc[col_e]; softmax + loss ----------------
__global__ void k_edge_head(const int* __restrict__ row, const int* __restrict__ col,
                            const int* __restrict__ label, float* __restrict__ logits) {
    __shared__ float red[256];
    const int tid = threadIdx.x;
    const int e = blockIdx.x * 256 + tid;
    float myloss = 0.f;
    if (e < NE) {
        int r = row[e], c = col[e];
        const float4* prp = (const float4*)(d_pr + (size_t)r * PSTR);
        const float4* pcp = (const float4*)(d_pc + (size_t)c * PSTR);
        float acc[PSTR];
#pragma unroll
        for (int j = 0; j < 3; j++) {
            float4 a = __ldg(prp + j);
            float4 b = __ldg(pcp + j);
            acc[j * 4 + 0] = a.x + b.x;
            acc[j * 4 + 1] = a.y + b.y;
            acc[j * 4 + 2] = a.z + b.z;
            acc[j * 4 + 3] = a.w + b.w;
        }
        float m = acc[0];
#pragma unroll
        for (int cc = 1; cc < NC; cc++) m = fmaxf(m, acc[cc]);
        float s = 0.f;
#pragma unroll
        for (int cc = 0; cc < NC; cc++) s += expf(acc[cc] - m);
        float lse = m + logf(s);
        myloss = lse - acc[label[e]];
        float* lp = logits + (size_t)e * NC;
#pragma unroll
        for (int cc = 0; cc < NC; cc++) lp[cc] = acc[cc];
    }
    red[tid] = myloss;
    __syncthreads();
    for (int s2 = 128; s2 > 0; s2 >>= 1) {
        if (tid < s2) red[tid] += red[tid + s2];
        __syncthreads();
    }
    if (tid == 0) atomicAdd(&d_loss, red[0]);
}

__global__ void k_final(float* __restrict__ loss_out) {
    if (loss_out) loss_out[0] = d_loss * (1.0f / (float)NE);
}

// ---------------- launch ----------------
extern "C" void kernel_launch(void* const* d_in, const int* in_sizes, int n_in,
                              void* d_out, int out_size) {
    const float* feat = (const float*)d_in[0];
    const float* W1   = (const float*)d_in[1];
    const float* b1   = (const float*)d_in[2];
    const float* W2   = (const float*)d_in[3];
    const float* b2   = (const float*)d_in[4];
    const float* Wfc  = (const float*)d_in[5];
    const float* bfc  = (const float*)d_in[6];
    const int*   row  = (const int*)d_in[7];
    const int*   col  = (const int*)d_in[8];
    const int*   lab  = (const int*)d_in[9];

    float* out = (float*)d_out;
    float* lossp;
    float* logits;
    if (out_size == NE * NC + 1) { lossp = out; logits = out + 1; }
    else                         { lossp = nullptr; logits = out; }

    void* ph = nullptr;
    cudaGetSymbolAddress(&ph, d_h);
    const float* h1 = (const float*)ph;

    // One-time side-stream/event setup (host-side resources only; no device mem).
    static cudaStream_t s_side = nullptr;
    static cudaEvent_t  evFork = nullptr, evB = nullptr;
    if (s_side == nullptr) {
        cudaStreamCreateWithFlags(&s_side, cudaStreamNonBlocking);
        cudaEventCreateWithFlags(&evFork, cudaEventDisableTiming);
        cudaEventCreateWithFlags(&evB, cudaEventDisableTiming);
    }

    const int TB = 256;
    const int nb_nodes = (NN + TB - 1) / TB;
    const int nb_edges = (NE + TB - 1) / TB;
    const int nb_gemm  = (NN + 63) / 64;
    const int nb_aggr  = (NN * 32 + TB - 1) / TB;
    const int nb_proj  = (NN + 127) / 128;

    // FORK: the side stream must join the capture via an event recorded in
    // the capturing (main) stream BEFORE any work is launched on it.
    cudaEventRecord(evFork, 0);
    cudaStreamWaitEvent(s_side, evFork, 0);

    // main stream: gemm1 starts immediately (depends only on inputs)
    k_gemm<<<nb_gemm, TB>>>(feat, W1, b1);

    // side stream: preamble + CSR build, overlapping gemm1
    k_init<<<nb_nodes, TB, 0, s_side>>>();
    k_hist<<<nb_edges, TB, 0, s_side>>>(row, col);
    k_dinv<<<nb_nodes, TB, 0, s_side>>>();
    k_scan1<<<NBLK, 256, 0, s_side>>>();
    k_scan2<<<1, 32, 0, s_side>>>();
    k_scan3<<<nb_nodes, TB, 0, s_side>>>();
    k_fill<<<nb_edges, TB, 0, s_side>>>(row, col);
    cudaEventRecord(evB, s_side);

    // JOIN: aggr needs CSR + dinv + g
    cudaStreamWaitEvent(0, evB, 0);
    k_aggr<<<nb_aggr, TB>>>();            // -> d_h = h1

    // conv 2
    k_gemm<<<nb_gemm, TB>>>(h1, W2, b2);
    k_aggr<<<nb_aggr, TB>>>();            // -> d_h = h2

    // edge head: per-node projection, then per-edge add + softmax
    k_proj<<<nb_proj, 128>>>(Wfc, bfc);
    k_edge_head<<<nb_edges, TB>>>(row, col, lab, logits);
    k_final<<<1, 1>>>(lossp);
}

// round 16
// speedup vs baseline: 2.4198x; 1.3754x over previous
#include <cuda_runtime.h>
#include <cstdint>

#define NN 50000
#define NE 600000
#define HF 128
#define NC 10
#define PSTR 12                  // padded projection row stride (floats)
#define NBLK ((NN + 511) / 512)  // 98 scan blocks

// ---------------- scratch (static device globals; no allocation) ----------------
__device__ __align__(16) float d_g[(size_t)NN * HF];    // Y = M X
__device__ __align__(16) float d_h[(size_t)NN * HF];    // Z = M Y = M^2 X
__device__ __align__(16) float d_pr[(size_t)NN * PSTR]; // per-node row-endpoint logits part
__device__ __align__(16) float d_pc[(size_t)NN * PSTR]; // per-node col-endpoint logits part
__device__ __align__(16) float d_wcomb[HF * HF];        // W2 @ W1
__device__ __align__(16) float d_wproj[20 * HF];        // [Wr;Wc] @ Wcomb
__device__ float d_v1[20];       // [Wr;Wc] @ (W2 b1)
__device__ float d_v2[20];       // [Wr;Wc] @ b2
__device__ float d_m[NN];        // m = M 1
__device__ float d_u[NN];        // u = M m
__device__ int   d_deg[NN];      // row-degree + 1 (norm)
__device__ float d_dinv[NN];
__device__ int   d_cnt[NN];      // col histogram (CSR)
__device__ int   d_start[NN];    // CSR offsets
__device__ int   d_ptr[NN];      // CSR fill cursors
__device__ int   d_csr[NE];      // source row per CSR slot
__device__ int   d_bsum[128];    // scan block sums
__device__ int   d_boff[128];    // scan block offsets
__device__ float d_loss;

#define FFMA2(acc, a, b) asm("fma.rn.f32x2 %0, %1, %2, %0;" : "+l"(acc) : "l"(a), "l"(b))

// ---------------- init ----------------
__global__ void k_init() {
    int i = blockIdx.x * blockDim.x + threadIdx.x;
    if (i < NN) { d_deg[i] = 1; d_cnt[i] = 0; }
    if (i == 0) d_loss = 0.f;
}

// row-degree (norm) + col histogram (CSR) in one pass
__global__ void k_hist(const int* __restrict__ row, const int* __restrict__ col) {
    int e = blockIdx.x * blockDim.x + threadIdx.x;
    if (e < NE) {
        atomicAdd(&d_deg[row[e]], 1);
        atomicAdd(&d_cnt[col[e]], 1);
    }
}

__global__ void k_dinv() {
    int i = blockIdx.x * blockDim.x + threadIdx.x;
    if (i < NN) d_dinv[i] = rsqrtf((float)d_deg[i]);
}

// ---------------- multi-block exclusive scan of d_cnt ----------------
__global__ void k_scan1() {
    __shared__ int wsum[8];
    const int t = threadIdx.x;
    const int base = blockIdx.x * 512 + t * 2;
    int c0 = (base < NN) ? d_cnt[base] : 0;
    int c1 = (base + 1 < NN) ? d_cnt[base + 1] : 0;
    int s = c0 + c1;
    int v = s;
#pragma unroll
    for (int o = 1; o < 32; o <<= 1) {
        int u = __shfl_up_sync(0xffffffffu, v, o);
        if ((t & 31) >= o) v += u;
    }
    if ((t & 31) == 31) wsum[t >> 5] = v;
    __syncthreads();
    if (t < 8) {
        int w = wsum[t];
#pragma unroll
        for (int o = 1; o < 8; o <<= 1) {
            int u = __shfl_up_sync(0xffu, w, o);
            if (t >= o) w += u;
        }
        wsum[t] = w;
    }
    __syncthreads();
    int pre = v - s + ((t >= 32) ? wsum[(t >> 5) - 1] : 0);
    if (base < NN) d_start[base] = pre;
    if (base + 1 < NN) d_start[base + 1] = pre + c0;
    if (t == 255) d_bsum[blockIdx.x] = wsum[7];
}

__global__ void k_scan2() {
    const int l = threadIdx.x;
    int c[4];
    int s = 0;
#pragma unroll
    for (int i = 0; i < 4; i++) {
        int idx = l * 4 + i;
        c[i] = (idx < NBLK) ? d_bsum[idx] : 0;
        s += c[i];
    }
    int v = s;
#pragma unroll
    for (int o = 1; o < 32; o <<= 1) {
        int u = __shfl_up_sync(0xffffffffu, v, o);
        if (l >= o) v += u;
    }
    int ex = v - s;
#pragma unroll
    for (int i = 0; i < 4; i++) {
        int idx = l * 4 + i;
        if (idx < NBLK) d_boff[idx] = ex;
        ex += c[i];
    }
}

__global__ void k_scan3() {
    int i = blockIdx.x * blockDim.x + threadIdx.x;
    if (i < NN) {
        int v = d_start[i] + d_boff[i >> 9];
        d_start[i] = v;
        d_ptr[i] = v;
    }
}

__global__ void k_fill(const int* __restrict__ row, const int* __restrict__ col) {
    int e = blockIdx.x * blockDim.x + threadIdx.x;
    if (e < NE) {
        int c = col[e];
        int slot = atomicAdd(&d_ptr[c], 1);
        d_csr[slot] = row[e];
    }
}

// ---------------- tiny weight-composition kernels (hidden on side stream) ----------------
// Wcomb = W2 @ W1   (both [128,128] row-major)
__global__ void k_wcomb(const float* __restrict__ W1, const float* __restrict__ W2) {
    const int i = blockIdx.x;     // 0..127
    const int j = threadIdx.x;    // 0..127
    float acc = 0.f;
#pragma unroll 8
    for (int k = 0; k < HF; k++)
        acc = fmaf(__ldg(W2 + i * HF + k), __ldg(W1 + k * HF + j), acc);
    d_wcomb[i * HF + j] = acc;
}

// Wproj[t] = Wfc_row(t) @ Wcomb  (t<10: Wr rows; t>=10: Wc rows)
__global__ void k_wproj(const float* __restrict__ Wfc) {
    const int t = blockIdx.x;     // 0..19
    const int j = threadIdx.x;    // 0..127
    const float* wrow = Wfc + ((t < 10) ? (size_t)t * 256 : (size_t)(t - 10) * 256 + 128);
    float acc = 0.f;
#pragma unroll 8
    for (int k = 0; k < HF; k++)
        acc = fmaf(__ldg(wrow + k), d_wcomb[k * HF + j], acc);
    d_wproj[t * HF + j] = acc;
}

// v1 = [Wr;Wc] @ (W2 b1),  v2 = [Wr;Wc] @ b2
__global__ void k_vecs(const float* __restrict__ W2, const float* __restrict__ b1,
                       const float* __restrict__ Wfc, const float* __restrict__ b2) {
    __shared__ float sbW[HF];
    const int tid = threadIdx.x;  // 128
    float acc = 0.f;
#pragma unroll 8
    for (int j = 0; j < HF; j++)
        acc = fmaf(__ldg(W2 + tid * HF + j), __ldg(b1 + j), acc);
    sbW[tid] = acc;
    __syncthreads();
    if (tid < 20) {
        const float* wrow = Wfc + ((tid < 10) ? (size_t)tid * 256 : (size_t)(tid - 10) * 256 + 128);
        float a1 = 0.f, a2 = 0.f;
        for (int k = 0; k < HF; k++) {
            float w = __ldg(wrow + k);
            a1 = fmaf(w, sbW[k], a1);
            a2 = fmaf(w, __ldg(b2 + k), a2);
        }
        d_v1[tid] = a1;
        d_v2[tid] = a2;
    }
}

// ---------------- CSR aggregate: dst[n] = dv*(dv*src[n] + sum_e dinv[r]*src[r]),
//                  m_out[n]   = dv*(dv*ms[n] + sum_e dinv[r]*ms[r])  (ms = m_in or 1)
__global__ void k_agg(const float4* __restrict__ src, float4* __restrict__ dst,
                      const float* __restrict__ m_in, float* __restrict__ m_out) {
    int gw = (blockIdx.x * blockDim.x + threadIdx.x) >> 5;
    if (gw >= NN) return;
    const int lane = threadIdx.x & 31;
    const int s = d_start[gw];
    const int cnt = d_cnt[gw];
    const float dv = d_dinv[gw];

    float4 sv = __ldg(src + (size_t)gw * 32 + lane);   // self loop
    float4 acc;
    acc.x = dv * sv.x; acc.y = dv * sv.y; acc.z = dv * sv.z; acc.w = dv * sv.w;
    float msum = 0.f;

    for (int j0 = 0; j0 < cnt; j0 += 32) {
        int r = 0;
        float dvl = 0.f, mw = 0.f;
        if (j0 + lane < cnt) {
            r = __ldg(d_csr + s + j0 + lane);
            dvl = __ldg(d_dinv + r);
            mw = dvl * (m_in ? __ldg(m_in + r) : 1.f);
        }
        int m = min(32, cnt - j0);
        int k = 0;
        for (; k + 4 <= m; k += 4) {
            int r0 = __shfl_sync(0xffffffffu, r, k + 0);
            int r1 = __shfl_sync(0xffffffffu, r, k + 1);
            int r2 = __shfl_sync(0xffffffffu, r, k + 2);
            int r3 = __shfl_sync(0xffffffffu, r, k + 3);
            float w0 = __shfl_sync(0xffffffffu, dvl, k + 0);
            float w1 = __shfl_sync(0xffffffffu, dvl, k + 1);
            float w2 = __shfl_sync(0xffffffffu, dvl, k + 2);
            float w3 = __shfl_sync(0xffffffffu, dvl, k + 3);
            float q0 = __shfl_sync(0xffffffffu, mw, k + 0);
            float q1 = __shfl_sync(0xffffffffu, mw, k + 1);
            float q2 = __shfl_sync(0xffffffffu, mw, k + 2);
            float q3 = __shfl_sync(0xffffffffu, mw, k + 3);
            float4 v0 = __ldg(src + (size_t)r0 * 32 + lane);
            float4 v1 = __ldg(src + (size_t)r1 * 32 + lane);
            float4 v2 = __ldg(src + (size_t)r2 * 32 + lane);
            float4 v3 = __ldg(src + (size_t)r3 * 32 + lane);
            msum += (q0 + q1) + (q2 + q3);
            acc.x = fmaf(w0, v0.x, fmaf(w1, v1.x, fmaf(w2, v2.x, fmaf(w3, v3.x, acc.x))));
            acc.y = fmaf(w0, v0.y, fmaf(w1, v1.y, fmaf(w2, v2.y, fmaf(w3, v3.y, acc.y))));
            acc.z = fmaf(w0, v0.z, fmaf(w1, v1.z, fmaf(w2, v2.z, fmaf(w3, v3.z, acc.z))));
            acc.w = fmaf(w0, v0.w, fmaf(w1, v1.w, fmaf(w2, v2.w, fmaf(w3, v3.w, acc.w))));
        }
        for (; k < m; k++) {
            int rr = __shfl_sync(0xffffffffu, r, k);
            float ww = __shfl_sync(0xffffffffu, dvl, k);
            float qq = __shfl_sync(0xffffffffu, mw, k);
            float4 v = __ldg(src + (size_t)rr * 32 + lane);
            msum += qq;
            acc.x = fmaf(ww, v.x, acc.x);
            acc.y = fmaf(ww, v.y, acc.y);
            acc.z = fmaf(ww, v.z, acc.z);
            acc.w = fmaf(ww, v.w, acc.w);
        }
    }
    acc.x *= dv; acc.y *= dv; acc.z *= dv; acc.w *= dv;
    dst[(size_t)gw * 32 + lane] = acc;
    if (lane == 0) {
        float m_self = m_in ? __ldg(m_in + gw) : 1.f;
        m_out[gw] = dv * (dv * m_self + msum);
    }
}

// ---------------- per-node projection: [pr;pc][n] = Wproj@Z[n] + u[n]*v1 + m[n]*v2 (+bfc) ----------------
__global__ void k_proj2(const float* __restrict__ bfc) {
    __shared__ __align__(16) float ws[20 * HF];
    __shared__ float sv1[20], sv2[20], bs[NC];
    const int tid = threadIdx.x;  // 128
    for (int i = tid; i < 20 * HF; i += 128) ws[i] = d_wproj[i];
    if (tid < 20) { sv1[tid] = d_v1[tid]; sv2[tid] = d_v2[tid]; }
    if (tid < NC) bs[tid] = bfc[tid];
    __syncthreads();

    const int n = blockIdx.x * 128 + tid;
    if (n >= NN) return;

    unsigned long long a[20];
#pragma unroll
    for (int t = 0; t < 20; t++) a[t] = 0ull;

    // FULL row: 128 floats = 32 ulonglong2 chunks of 4 floats each
    const ulonglong2* zp = (const ulonglong2*)(d_h + (size_t)n * HF);
#pragma unroll
    for (int q = 0; q < 32; q++) {
        ulonglong2 xv = __ldg(zp + q);
#pragma unroll
        for (int t = 0; t < 20; t++) {
            ulonglong2 wv = *(const ulonglong2*)&ws[t * HF + q * 4];
            FFMA2(a[t], xv.x, wv.x);
            FFMA2(a[t], xv.y, wv.y);
        }
    }

    const float un = d_u[n];
    const float mn = d_m[n];
    float outr[PSTR], outc[PSTR];
#pragma unroll
    for (int t = 0; t < 10; t++) {
        float lo, hi;
        asm("mov.b64 {%0, %1}, %2;" : "=f"(lo), "=f"(hi) : "l"(a[t]));
        outr[t] = lo + hi + un * sv1[t] + mn * sv2[t] + bs[t];
        asm("mov.b64 {%0, %1}, %2;" : "=f"(lo), "=f"(hi) : "l"(a[t + 10]));
        outc[t] = lo + hi + un * sv1[t + 10] + mn * sv2[t + 10];
    }
    outr[10] = 0.f; outr[11] = 0.f;
    outc[10] = 0.f; outc[11] = 0.f;

    float4* prp = (float4*)(d_pr + (size_t)n * PSTR);
    float4* pcp = (float4*)(d_pc + (size_t)n * PSTR);
#pragma unroll
    for (int j = 0; j < 3; j++) {
        prp[j] = *(const float4*)&outr[j * 4];
        pcp[j] = *(const float4*)&outc[j * 4];
    }
}

// ---------------- edge head: logits[e] = pr[row_e] + pc[col_e]; softmax + loss ----------------
__global__ void k_edge_head(const int* __restrict__ row, const int* __restrict__ col,
                            const int* __restrict__ label, float* __restrict__ logits) {
    __shared__ float red[256];
    const int tid = threadIdx.x;
    const int e = blockIdx.x * 256 + tid;
    float myloss = 0.f;
    if (e < NE) {
        int r = row[e], c = col[e];
        const float4* prp = (const float4*)(d_pr + (size_t)r * PSTR);
        const float4* pcp = (const float4*)(d_pc + (size_t)c * PSTR);
        float acc[PSTR];
#pragma unroll
        for (int j = 0; j < 3; j++) {
            float4 a = __ldg(prp + j);
            float4 b = __ldg(pcp + j);
            acc[j * 4 + 0] = a.x + b.x;
            acc[j * 4 + 1] = a.y + b.y;
            acc[j * 4 + 2] = a.z + b.z;
            acc[j * 4 + 3] = a.w + b.w;
        }
        float m = acc[0];
#pragma unroll
        for (int cc = 1; cc < NC; cc++) m = fmaxf(m, acc[cc]);
        float s = 0.f;
#pragma unroll
        for (int cc = 0; cc < NC; cc++) s += expf(acc[cc] - m);
        float lse = m + logf(s);
        myloss = lse - acc[label[e]];
        float* lp = logits + (size_t)e * NC;
#pragma unroll
        for (int cc = 0; cc < NC; cc++) lp[cc] = acc[cc];
    }
    red[tid] = myloss;
    __syncthreads();
    for (int s2 = 128; s2 > 0; s2 >>= 1) {
        if (tid < s2) red[tid] += red[tid + s2];
        __syncthreads();
    }
    if (tid == 0) atomicAdd(&d_loss, red[0]);
}

__global__ void k_final(float* __restrict__ loss_out) {
    if (loss_out) loss_out[0] = d_loss * (1.0f / (float)NE);
}

// ---------------- launch ----------------
extern "C" void kernel_launch(void* const* d_in, const int* in_sizes, int n_in,
                              void* d_out, int out_size) {
    const float* feat = (const float*)d_in[0];
    const float* W1   = (const float*)d_in[1];
    const float* b1   = (const float*)d_in[2];
    const float* W2   = (const float*)d_in[3];
    const float* b2   = (const float*)d_in[4];
    const float* Wfc  = (const float*)d_in[5];
    const float* bfc  = (const float*)d_in[6];
    const int*   row  = (const int*)d_in[7];
    const int*   col  = (const int*)d_in[8];
    const int*   lab  = (const int*)d_in[9];

    float* out = (float*)d_out;
    float* lossp;
    float* logits;
    if (out_size == NE * NC + 1) { lossp = out; logits = out + 1; }
    else                         { lossp = nullptr; logits = out; }

    void *pg = nullptr, *phh = nullptr, *pm = nullptr, *pu = nullptr;
    cudaGetSymbolAddress(&pg, d_g);
    cudaGetSymbolAddress(&phh, d_h);
    cudaGetSymbolAddress(&pm, d_m);
    cudaGetSymbolAddress(&pu, d_u);

    // One-time side-stream/event setup (host-side resources only; no device mem).
    static cudaStream_t s_side = nullptr;
    static cudaEvent_t  evFork = nullptr, evW = nullptr;
    if (s_side == nullptr) {
        cudaStreamCreateWithFlags(&s_side, cudaStreamNonBlocking);
        cudaEventCreateWithFlags(&evFork, cudaEventDisableTiming);
        cudaEventCreateWithFlags(&evW, cudaEventDisableTiming);
    }

    const int TB = 256;
    const int nb_nodes = (NN + TB - 1) / TB;
    const int nb_edges = (NE + TB - 1) / TB;
    const int nb_aggr  = (NN * 32 + TB - 1) / TB;
    const int nb_proj  = (NN + 127) / 128;

    // FORK: side stream joins capture via event recorded in main stream.
    cudaEventRecord(evFork, 0);
    cudaStreamWaitEvent(s_side, evFork, 0);

    // side stream: weight composition (independent of graph path, fully hidden)
    k_wcomb<<<128, 128, 0, s_side>>>(W1, W2);
    k_wproj<<<20, 128, 0, s_side>>>(Wfc);
    k_vecs<<<1, 128, 0, s_side>>>(W2, b1, Wfc, b2);
    cudaEventRecord(evW, s_side);

    // main stream: preamble + CSR build
    k_init<<<nb_nodes, TB>>>();
    k_hist<<<nb_edges, TB>>>(row, col);
    k_dinv<<<nb_nodes, TB>>>();
    k_scan1<<<NBLK, 256>>>();
    k_scan2<<<1, 32>>>();
    k_scan3<<<nb_nodes, TB>>>();
    k_fill<<<nb_edges, TB>>>(row, col);

    // two aggregations of X:  Y = M X (+m),  Z = M Y (+u)
    k_agg<<<nb_aggr, TB>>>((const float4*)feat, (float4*)pg, nullptr, (float*)pm);
    k_agg<<<nb_aggr, TB>>>((const float4*)pg, (float4*)phh, (const float*)pm, (float*)pu);

    // JOIN: projection needs composed weights
    cudaStreamWaitEvent(0, evW, 0);
    k_proj2<<<nb_proj, 128>>>(bfc);
    k_edge_head<<<nb_edges, TB>>>(row, col, lab, logits);
    k_final<<<1, 1>>>(lossp);
}

// round 17
// speedup vs baseline: 2.4678x; 1.0198x over previous
#include <cuda_runtime.h>
#include <cstdint>

#define NN 50000
#define NE 600000
#define HF 128
#define NC 10
#define PSTR 12                  // padded projection row stride (floats)
#define NBLK ((NN + 511) / 512)  // 98 scan blocks

// ---------------- scratch (static device globals; no allocation) ----------------
__device__ __align__(16) float d_g[(size_t)NN * HF];    // Y = M X
__device__ __align__(16) float d_h[(size_t)NN * HF];    // Z = M Y = M^2 X
__device__ __align__(16) float d_pr[(size_t)NN * PSTR]; // per-node row-endpoint logits part
__device__ __align__(16) float d_pc[(size_t)NN * PSTR]; // per-node col-endpoint logits part
__device__ __align__(16) float d_wcomb[HF * HF];        // W2 @ W1
__device__ __align__(16) float d_wproj[20 * HF];        // [Wr;Wc] @ Wcomb
__device__ float d_v1[20];       // [Wr;Wc] @ (W2 b1)
__device__ float d_v2[20];       // [Wr;Wc] @ b2
__device__ float d_m[NN];        // m = M 1
__device__ float d_u[NN];        // u = M m
__device__ int   d_deg[NN];      // row-degree + 1 (norm)
__device__ float d_dinv[NN];
__device__ int   d_cnt[NN];      // col histogram (CSR)
__device__ int   d_start[NN];    // CSR offsets
__device__ int   d_ptr[NN];      // CSR fill cursors
__device__ int   d_csr[NE];      // source row per CSR slot
__device__ int   d_bsum[128];    // scan block sums
__device__ float d_loss;
__device__ int   d_done;

#define FFMA2(acc, a, b) asm("fma.rn.f32x2 %0, %1, %2, %0;" : "+l"(acc) : "l"(a), "l"(b))

// ---------------- init ----------------
__global__ void k_init() {
    int i = blockIdx.x * blockDim.x + threadIdx.x;
    if (i < NN) { d_deg[i] = 1; d_cnt[i] = 0; }
    if (i == 0) { d_loss = 0.f; d_done = 0; }
}

// row-degree (norm) + col histogram (CSR) in one pass
__global__ void k_hist(const int* __restrict__ row, const int* __restrict__ col) {
    int e = blockIdx.x * blockDim.x + threadIdx.x;
    if (e < NE) {
        atomicAdd(&d_deg[row[e]], 1);
        atomicAdd(&d_cnt[col[e]], 1);
    }
}

// ---------------- scan phase 1 (+ fused dinv): local scan + block sums ----------------
__global__ void k_scan1() {
    __shared__ int wsum[8];
    const int t = threadIdx.x;
    const int base = blockIdx.x * 512 + t * 2;
    int c0 = (base < NN) ? d_cnt[base] : 0;
    int c1 = (base + 1 < NN) ? d_cnt[base + 1] : 0;
    // fused dinv (d_deg final after hist)
    if (base < NN) d_dinv[base] = rsqrtf((float)d_deg[base]);
    if (base + 1 < NN) d_dinv[base + 1] = rsqrtf((float)d_deg[base + 1]);
    int s = c0 + c1;
    int v = s;
#pragma unroll
    for (int o = 1; o < 32; o <<= 1) {
        int u = __shfl_up_sync(0xffffffffu, v, o);
        if ((t & 31) >= o) v += u;
    }
    if ((t & 31) == 31) wsum[t >> 5] = v;
    __syncthreads();
    if (t < 8) {
        int w = wsum[t];
#pragma unroll
        for (int o = 1; o < 8; o <<= 1) {
            int u = __shfl_up_sync(0xffu, w, o);
            if (t >= o) w += u;
        }
        wsum[t] = w;
    }
    __syncthreads();
    int pre = v - s + ((t >= 32) ? wsum[(t >> 5) - 1] : 0);
    if (base < NN) d_start[base] = pre;
    if (base + 1 < NN) d_start[base + 1] = pre + c0;
    if (t == 255) d_bsum[blockIdx.x] = wsum[7];
}

// ---------------- scan phase 2: add block offsets (computed redundantly per block) ----------------
// 256-thread blocks, 2 scan3-blocks per scan1-chunk: each block's offset = sum(d_bsum[0 .. b/2)).
__global__ void k_scan3() {
    __shared__ int soff;
    const int t = threadIdx.x;
    const int target = blockIdx.x >> 1;   // scan1 chunk index of this block
    if (t < 32) {
        int ssum = 0;
        for (int i = t; i < target; i += 32) ssum += d_bsum[i];
#pragma unroll
        for (int o = 16; o > 0; o >>= 1) ssum += __shfl_down_sync(0xffffffffu, ssum, o);
        if (t == 0) soff = ssum;
    }
    __syncthreads();
    int i = blockIdx.x * 256 + t;
    if (i < NN) {
        int v = d_start[i] + soff;
        d_start[i] = v;
        d_ptr[i] = v;
    }
}

__global__ void k_fill(const int* __restrict__ row, const int* __restrict__ col) {
    int e = blockIdx.x * blockDim.x + threadIdx.x;
    if (e < NE) {
        int c = col[e];
        int slot = atomicAdd(&d_ptr[c], 1);
        d_csr[slot] = row[e];
    }
}

// ---------------- tiny weight-composition kernels (hidden on side stream) ----------------
__global__ void k_wcomb(const float* __restrict__ W1, const float* __restrict__ W2) {
    const int i = blockIdx.x;
    const int j = threadIdx.x;
    float acc = 0.f;
#pragma unroll 8
    for (int k = 0; k < HF; k++)
        acc = fmaf(__ldg(W2 + i * HF + k), __ldg(W1 + k * HF + j), acc);
    d_wcomb[i * HF + j] = acc;
}

__global__ void k_wproj(const float* __restrict__ Wfc) {
    const int t = blockIdx.x;
    const int j = threadIdx.x;
    const float* wrow = Wfc + ((t < 10) ? (size_t)t * 256 : (size_t)(t - 10) * 256 + 128);
    float acc = 0.f;
#pragma unroll 8
    for (int k = 0; k < HF; k++)
        acc = fmaf(__ldg(wrow + k), d_wcomb[k * HF + j], acc);
    d_wproj[t * HF + j] = acc;
}

__global__ void k_vecs(const float* __restrict__ W2, const float* __restrict__ b1,
                       const float* __restrict__ Wfc, const float* __restrict__ b2) {
    __shared__ float sbW[HF];
    const int tid = threadIdx.x;
    float acc = 0.f;
#pragma unroll 8
    for (int j = 0; j < HF; j++)
        acc = fmaf(__ldg(W2 + tid * HF + j), __ldg(b1 + j), acc);
    sbW[tid] = acc;
    __syncthreads();
    if (tid < 20) {
        const float* wrow = Wfc + ((tid < 10) ? (size_t)tid * 256 : (size_t)(tid - 10) * 256 + 128);
        float a1 = 0.f, a2 = 0.f;
        for (int k = 0; k < HF; k++) {
            float w = __ldg(wrow + k);
            a1 = fmaf(w, sbW[k], a1);
            a2 = fmaf(w, __ldg(b2 + k), a2);
        }
        d_v1[tid] = a1;
        d_v2[tid] = a2;
    }
}

// ---------------- CSR aggregate (8-deep gather unroll) ----------------
// dst[n] = dv*(dv*src[n] + sum_e dinv[r]*src[r]); m_out likewise on scalars.
__global__ void k_agg(const float4* __restrict__ src, float4* __restrict__ dst,
                      const float* __restrict__ m_in, float* __restrict__ m_out) {
    int gw = (blockIdx.x * blockDim.x + threadIdx.x) >> 5;
    if (gw >= NN) return;
    const int lane = threadIdx.x & 31;
    const int s = d_start[gw];
    const int cnt = d_cnt[gw];
    const float dv = d_dinv[gw];

    float4 sv = __ldg(src + (size_t)gw * 32 + lane);   // self loop
    float4 acc;
    acc.x = dv * sv.x; acc.y = dv * sv.y; acc.z = dv * sv.z; acc.w = dv * sv.w;
    float msum = 0.f;

    for (int j0 = 0; j0 < cnt; j0 += 32) {
        int r = 0;
        float dvl = 0.f, mw = 0.f;
        if (j0 + lane < cnt) {
            r = __ldg(d_csr + s + j0 + lane);
            dvl = __ldg(d_dinv + r);
            mw = dvl * (m_in ? __ldg(m_in + r) : 1.f);
        }
        int m = min(32, cnt - j0);
        int k = 0;
        for (; k + 8 <= m; k += 8) {
            int ri[8]; float wi[8], qi[8]; float4 vi[8];
#pragma unroll
            for (int u = 0; u < 8; u++) {
                ri[u] = __shfl_sync(0xffffffffu, r, k + u);
                wi[u] = __shfl_sync(0xffffffffu, dvl, k + u);
                qi[u] = __shfl_sync(0xffffffffu, mw, k + u);
            }
#pragma unroll
            for (int u = 0; u < 8; u++) vi[u] = __ldg(src + (size_t)ri[u] * 32 + lane);
#pragma unroll
            for (int u = 0; u < 8; u++) {
                msum += qi[u];
                acc.x = fmaf(wi[u], vi[u].x, acc.x);
                acc.y = fmaf(wi[u], vi[u].y, acc.y);
                acc.z = fmaf(wi[u], vi[u].z, acc.z);
                acc.w = fmaf(wi[u], vi[u].w, acc.w);
            }
        }
        for (; k + 4 <= m; k += 4) {
            int ri[4]; float wi[4], qi[4]; float4 vi[4];
#pragma unroll
            for (int u = 0; u < 4; u++) {
                ri[u] = __shfl_sync(0xffffffffu, r, k + u);
                wi[u] = __shfl_sync(0xffffffffu, dvl, k + u);
                qi[u] = __shfl_sync(0xffffffffu, mw, k + u);
            }
#pragma unroll
            for (int u = 0; u < 4; u++) vi[u] = __ldg(src + (size_t)ri[u] * 32 + lane);
#pragma unroll
            for (int u = 0; u < 4; u++) {
                msum += qi[u];
                acc.x = fmaf(wi[u], vi[u].x, acc.x);
                acc.y = fmaf(wi[u], vi[u].y, acc.y);
                acc.z = fmaf(wi[u], vi[u].z, acc.z);
                acc.w = fmaf(wi[u], vi[u].w, acc.w);
            }
        }
        for (; k < m; k++) {
            int rr = __shfl_sync(0xffffffffu, r, k);
            float ww = __shfl_sync(0xffffffffu, dvl, k);
            float qq = __shfl_sync(0xffffffffu, mw, k);
            float4 v = __ldg(src + (size_t)rr * 32 + lane);
            msum += qq;
            acc.x = fmaf(ww, v.x, acc.x);
            acc.y = fmaf(ww, v.y, acc.y);
            acc.z = fmaf(ww, v.z, acc.z);
            acc.w = fmaf(ww, v.w, acc.w);
        }
    }
    acc.x *= dv; acc.y *= dv; acc.z *= dv; acc.w *= dv;
    dst[(size_t)gw * 32 + lane] = acc;
    if (lane == 0) {
        float m_self = m_in ? __ldg(m_in + gw) : 1.f;
        m_out[gw] = dv * (dv * m_self + msum);
    }
}

// ---------------- per-node projection ----------------
__global__ void k_proj2(const float* __restrict__ bfc) {
    __shared__ __align__(16) float ws[20 * HF];
    __shared__ float sv1[20], sv2[20], bs[NC];
    const int tid = threadIdx.x;  // 128
    for (int i = tid; i < 20 * HF; i += 128) ws[i] = d_wproj[i];
    if (tid < 20) { sv1[tid] = d_v1[tid]; sv2[tid] = d_v2[tid]; }
    if (tid < NC) bs[tid] = bfc[tid];
    __syncthreads();

    const int n = blockIdx.x * 128 + tid;
    if (n >= NN) return;

    unsigned long long a[20];
#pragma unroll
    for (int t = 0; t < 20; t++) a[t] = 0ull;

    const ulonglong2* zp = (const ulonglong2*)(d_h + (size_t)n * HF);
#pragma unroll
    for (int q = 0; q < 32; q++) {
        ulonglong2 xv = __ldg(zp + q);
#pragma unroll
        for (int t = 0; t < 20; t++) {
            ulonglong2 wv = *(const ulonglong2*)&ws[t * HF + q * 4];
            FFMA2(a[t], xv.x, wv.x);
            FFMA2(a[t], xv.y, wv.y);
        }
    }

    const float un = d_u[n];
    const float mn = d_m[n];
    float outr[PSTR], outc[PSTR];
#pragma unroll
    for (int t = 0; t < 10; t++) {
        float lo, hi;
        asm("mov.b64 {%0, %1}, %2;" : "=f"(lo), "=f"(hi) : "l"(a[t]));
        outr[t] = lo + hi + un * sv1[t] + mn * sv2[t] + bs[t];
        asm("mov.b64 {%0, %1}, %2;" : "=f"(lo), "=f"(hi) : "l"(a[t + 10]));
        outc[t] = lo + hi + un * sv1[t + 10] + mn * sv2[t + 10];
    }
    outr[10] = 0.f; outr[11] = 0.f;
    outc[10] = 0.f; outc[11] = 0.f;

    float4* prp = (float4*)(d_pr + (size_t)n * PSTR);
    float4* pcp = (float4*)(d_pc + (size_t)n * PSTR);
#pragma unroll
    for (int j = 0; j < 3; j++) {
        prp[j] = *(const float4*)&outr[j * 4];
        pcp[j] = *(const float4*)&outc[j * 4];
    }
}

// ---------------- edge head (+ fused final loss write via ticket) ----------------
__global__ void k_edge_head(const int* __restrict__ row, const int* __restrict__ col,
                            const int* __restrict__ label, float* __restrict__ logits,
                            float* __restrict__ loss_out) {
    __shared__ float red[256];
    const int tid = threadIdx.x;
    const int e = blockIdx.x * 256 + tid;
    float myloss = 0.f;
    if (e < NE) {
        int r = row[e], c = col[e];
        const float4* prp = (const float4*)(d_pr + (size_t)r * PSTR);
        const float4* pcp = (const float4*)(d_pc + (size_t)c * PSTR);
        float acc[PSTR];
#pragma unroll
        for (int j = 0; j < 3; j++) {
            float4 a = __ldg(prp + j);
            float4 b = __ldg(pcp + j);
            acc[j * 4 + 0] = a.x + b.x;
            acc[j * 4 + 1] = a.y + b.y;
            acc[j * 4 + 2] = a.z + b.z;
            acc[j * 4 + 3] = a.w + b.w;
        }
        float m = acc[0];
#pragma unroll
        for (int cc = 1; cc < NC; cc++) m = fmaxf(m, acc[cc]);
        float s = 0.f;
#pragma unroll
        for (int cc = 0; cc < NC; cc++) s += __expf(acc[cc] - m);
        float lse = m + __logf(s);
        myloss = lse - acc[label[e]];
        float* lp = logits + (size_t)e * NC;
#pragma unroll
        for (int cc = 0; cc < NC; cc++) lp[cc] = acc[cc];
    }
    red[tid] = myloss;
    __syncthreads();
    for (int s2 = 128; s2 > 0; s2 >>= 1) {
        if (tid < s2) red[tid] += red[tid + s2];
        __syncthreads();
    }
    if (tid == 0) {
        atomicAdd(&d_loss, red[0]);
        __threadfence();
        int t = atomicAdd(&d_done, 1);
        if (t == (int)gridDim.x - 1 && loss_out) {
            float total = atomicAdd(&d_loss, 0.f);   // ordered read
            loss_out[0] = total * (1.0f / (float)NE);
        }
    }
}

// ---------------- launch ----------------
extern "C" void kernel_launch(void* const* d_in, const int* in_sizes, int n_in,
                              void* d_out, int out_size) {
    const float* feat = (const float*)d_in[0];
    const float* W1   = (const float*)d_in[1];
    const float* b1   = (const float*)d_in[2];
    const float* W2   = (const float*)d_in[3];
    const float* b2   = (const float*)d_in[4];
    const float* Wfc  = (const float*)d_in[5];
    const float* bfc  = (const float*)d_in[6];
    const int*   row  = (const int*)d_in[7];
    const int*   col  = (const int*)d_in[8];
    const int*   lab  = (const int*)d_in[9];

    float* out = (float*)d_out;
    float* lossp;
    float* logits;
    if (out_size == NE * NC + 1) { lossp = out; logits = out + 1; }
    else                         { lossp = nullptr; logits = out; }

    void *pg = nullptr, *phh = nullptr, *pm = nullptr, *pu = nullptr;
    cudaGetSymbolAddress(&pg, d_g);
    cudaGetSymbolAddress(&phh, d_h);
    cudaGetSymbolAddress(&pm, d_m);
    cudaGetSymbolAddress(&pu, d_u);

    // One-time side-stream/event setup (host-side resources only; no device mem).
    static cudaStream_t s_side = nullptr;
    static cudaEvent_t  evFork = nullptr, evW = nullptr;
    if (s_side == nullptr) {
        cudaStreamCreateWithFlags(&s_side, cudaStreamNonBlocking);
        cudaEventCreateWithFlags(&evFork, cudaEventDisableTiming);
        cudaEventCreateWithFlags(&evW, cudaEventDisableTiming);
    }

    const int TB = 256;
    const int nb_nodes = (NN + TB - 1) / TB;
    const int nb_edges = (NE + TB - 1) / TB;
    const int nb_aggr  = (NN * 32 + TB - 1) / TB;
    const int nb_proj  = (NN + 127) / 128;

    // FORK: side stream joins capture via event recorded in main stream.
    cudaEventRecord(evFork, 0);
    cudaStreamWaitEvent(s_side, evFork, 0);

    // side stream: weight composition (independent of graph path, fully hidden)
    k_wcomb<<<128, 128, 0, s_side>>>(W1, W2);
    k_wproj<<<20, 128, 0, s_side>>>(Wfc);
    k_vecs<<<1, 128, 0, s_side>>>(W2, b1, Wfc, b2);
    cudaEventRecord(evW, s_side);

    // main stream: preamble + CSR build (5 launches)
    k_init<<<nb_nodes, TB>>>();
    k_hist<<<nb_edges, TB>>>(row, col);
    k_scan1<<<NBLK, 256>>>();
    k_scan3<<<nb_nodes, TB>>>();
    k_fill<<<nb_edges, TB>>>(row, col);

    // two aggregations of X:  Y = M X (+m),  Z = M Y (+u)
    k_agg<<<nb_aggr, TB>>>((const float4*)feat, (float4*)pg, nullptr, (float*)pm);
    k_agg<<<nb_aggr, TB>>>((const float4*)pg, (float4*)phh, (const float*)pm, (float*)pu);

    // JOIN: projection needs composed weights
    cudaStreamWaitEvent(0, evW, 0);
    k_proj2<<<nb_proj, 128>>>(bfc);
    k_edge_head<<<nb_edges, TB>>>(row, col, lab, logits, lossp);
}